// round 2
// baseline (speedup 1.0000x reference)
#include <cuda_runtime.h>
#include <math.h>

// Problem constants
#define Bv 32
#define Lv 4096
#define Hv 256
#define NLv 4
#define N2v 32
#define LN_EPS 1e-5f

// Big scratch buffers in device global memory (allocation-free rule)
__device__ float g_h[(size_t)Bv * Hv * Lv];   // activations (B,H,L)
__device__ float g_g[(size_t)Bv * Hv * Lv];   // gelu(S4D output)
__device__ float g_z[(size_t)Bv * Hv * Lv];   // GLU output

// ---------------------------------------------------------------------------
// Encoder: h[b,j,l] = x[b,l]*enc_w[j] + enc_b[j]   (CH=1)
// ---------------------------------------------------------------------------
__global__ void enc_kernel(const float* __restrict__ x,
                           const float* __restrict__ enc_w,
                           const float* __restrict__ enc_b) {
    size_t t = (size_t)blockIdx.x * blockDim.x + threadIdx.x;   // 8388608 threads
    size_t idx4 = t * 4;                                        // element index
    int l = (int)(idx4 & (Lv - 1));
    int j = (int)((idx4 >> 12) & (Hv - 1));
    int b = (int)(idx4 >> 20);
    float w = enc_w[j];
    float bias = enc_b[j];
    const float4 xv = *(const float4*)&x[(size_t)b * Lv + l];
    float4 o;
    o.x = fmaf(xv.x, w, bias);
    o.y = fmaf(xv.y, w, bias);
    o.z = fmaf(xv.z, w, bias);
    o.w = fmaf(xv.w, w, bias);
    *(float4*)&g_h[idx4] = o;
}

// ---------------------------------------------------------------------------
// S4D scan + D skip + exact GELU.
// 4 threads per (b,h) sequence, 8 complex states per thread (registers).
// Chunked smem staging of u for coalesced global traffic.
// ---------------------------------------------------------------------------
#define SEQ_PER_BLOCK 32
#define SCAN_THREADS 128
#define CHUNK 128

__global__ void __launch_bounds__(SCAN_THREADS)
scan_gelu_kernel(const float* __restrict__ log_dt,
                 const float* __restrict__ log_A_real,
                 const float* __restrict__ A_imag,
                 const float* __restrict__ C_re,
                 const float* __restrict__ C_im,
                 const float* __restrict__ Dp,
                 int layer) {
    __shared__ float su[SEQ_PER_BLOCK][CHUNK + 1];
    __shared__ float sy[SEQ_PER_BLOCK][CHUNK + 1];

    const int tid = threadIdx.x;
    const int seq_local = tid >> 2;   // 0..31
    const int sub = tid & 3;          // 0..3 (state group)
    const int seq = blockIdx.x * SEQ_PER_BLOCK + seq_local;   // 0..8191
    const int hh = seq & (Hv - 1);

    // Discretize: lambda = exp(dt*A), Ck = C*(lambda-1)/A, fold factor 2.
    const int pb = (layer * Hv + hh) * N2v + sub * 8;
    float lr[8], li[8], ckr[8], cki[8];
    const float dt = expf(log_dt[layer * Hv + hh]);
#pragma unroll
    for (int k = 0; k < 8; k++) {
        float Ar = -expf(log_A_real[pb + k]);
        float Ai = A_imag[pb + k];
        float dAr = Ar * dt, dAi = Ai * dt;
        float e = expf(dAr);
        float lrr = e * cosf(dAi);
        float lii = e * sinf(dAi);
        lr[k] = lrr; li[k] = lii;
        float cr = C_re[pb + k], ci = C_im[pb + k];
        float nr = cr * (lrr - 1.f) - ci * lii;
        float ni = cr * lii + ci * (lrr - 1.f);
        float inv = 1.f / (Ar * Ar + Ai * Ai);
        ckr[k] =  2.f * (nr * Ar + ni * Ai) * inv;
        cki[k] = -2.f * (ni * Ar - nr * Ai) * inv;  // signed so plain fma works
    }
    const float Dh = Dp[layer * Hv + hh];

    float sr[8], si[8];
#pragma unroll
    for (int k = 0; k < 8; k++) { sr[k] = 0.f; si[k] = 0.f; }

    const size_t base = (size_t)blockIdx.x * SEQ_PER_BLOCK * Lv;

    for (int c0 = 0; c0 < Lv; c0 += CHUNK) {
        __syncthreads();
        // cooperative coalesced load of u chunk
#pragma unroll
        for (int it = 0; it < (SEQ_PER_BLOCK * CHUNK) / SCAN_THREADS; it++) {
            int i = tid + it * SCAN_THREADS;
            int s = i >> 7;          // CHUNK=128
            int l = i & (CHUNK - 1);
            su[s][l] = g_h[base + (size_t)s * Lv + c0 + l];
        }
        __syncthreads();

        for (int l = 0; l < CHUNK; l++) {
            float u = su[seq_local][l];
            float acc = 0.f;
#pragma unroll
            for (int k = 0; k < 8; k++) {
                float nr = fmaf(lr[k], sr[k], u);
                nr = fmaf(-li[k], si[k], nr);
                float ni = fmaf(li[k], sr[k], lr[k] * si[k]);
                sr[k] = nr; si[k] = ni;
                acc = fmaf(ckr[k], nr, acc);
                acc = fmaf(cki[k], ni, acc);
            }
            acc += __shfl_xor_sync(0xffffffffu, acc, 1);
            acc += __shfl_xor_sync(0xffffffffu, acc, 2);
            float y = fmaf(Dh, u, acc);
            float gel = 0.5f * y * (1.f + erff(y * 0.70710678118654752f));
            if (sub == 0) sy[seq_local][l] = gel;
        }
        __syncthreads();
        // cooperative coalesced store of gelu chunk
#pragma unroll
        for (int it = 0; it < (SEQ_PER_BLOCK * CHUNK) / SCAN_THREADS; it++) {
            int i = tid + it * SCAN_THREADS;
            int s = i >> 7;
            int l = i & (CHUNK - 1);
            g_g[base + (size_t)s * Lv + c0 + l] = sy[s][l];
        }
    }
}

// ---------------------------------------------------------------------------
// GLU: Z[b,j,l] = a * sigmoid(g),
//   a = sum_k glu_w[j,k]     * G[b,k,l] + glu_b[j]
//   g = sum_k glu_w[j+256,k] * G[b,k,l] + glu_b[j+256]
// Tiled fp32 GEMM: block = 64 row-pairs x 128 cols, K looped in 16-chunks.
// 256 threads, each computes 4 row-pairs x 8 cols.
// ---------------------------------------------------------------------------
__global__ void __launch_bounds__(256)
glu_kernel(const float* __restrict__ glu_w,
           const float* __restrict__ glu_b,
           int layer) {
    __shared__ float sWa[16][68];
    __shared__ float sWg[16][68];
    __shared__ float sGt[16][132];

    const int tid = threadIdx.x;
    const int ttx = tid & 15;      // col group
    const int tty = tid >> 4;      // row group
    const int m0 = blockIdx.y * 64;            // row-pair base (0..192)
    const int n0 = blockIdx.x * 128;           // flat (b,l) col base
    const int b = n0 >> 12;
    const int l0 = n0 & (Lv - 1);

    const float* wbase = glu_w + (size_t)layer * 2 * Hv * Hv;
    const float* bbase = glu_b + (size_t)layer * 2 * Hv;

    float acc_a[4][8], acc_g[4][8];
#pragma unroll
    for (int r = 0; r < 4; r++)
#pragma unroll
        for (int c = 0; c < 8; c++) { acc_a[r][c] = 0.f; acc_g[r][c] = 0.f; }

    for (int kc = 0; kc < Hv; kc += 16) {
        __syncthreads();
        // load W tiles (a rows and g rows)
#pragma unroll
        for (int it = 0; it < 4; it++) {
            int i = tid + it * 256;            // 1024 elems
            int k = i & 15;
            int r = i >> 4;
            sWa[k][r] = wbase[(size_t)(m0 + r) * Hv + kc + k];
            sWg[k][r] = wbase[(size_t)(m0 + r + Hv) * Hv + kc + k];
        }
        // load G tile
#pragma unroll
        for (int it = 0; it < 8; it++) {
            int i = tid + it * 256;            // 2048 elems
            int c = i & 127;
            int k = i >> 7;
            sGt[k][c] = g_g[((size_t)(b * Hv + kc + k)) * Lv + l0 + c];
        }
        __syncthreads();

#pragma unroll
        for (int k = 0; k < 16; k++) {
            float4 wa = *(const float4*)&sWa[k][tty * 4];
            float4 wg = *(const float4*)&sWg[k][tty * 4];
            float4 gA = *(const float4*)&sGt[k][ttx * 8];
            float4 gB = *(const float4*)&sGt[k][ttx * 8 + 4];
            float gv[8] = {gA.x, gA.y, gA.z, gA.w, gB.x, gB.y, gB.z, gB.w};
            float wav[4] = {wa.x, wa.y, wa.z, wa.w};
            float wgv[4] = {wg.x, wg.y, wg.z, wg.w};
#pragma unroll
            for (int r = 0; r < 4; r++)
#pragma unroll
                for (int c = 0; c < 8; c++) {
                    acc_a[r][c] = fmaf(wav[r], gv[c], acc_a[r][c]);
                    acc_g[r][c] = fmaf(wgv[r], gv[c], acc_g[r][c]);
                }
        }
    }

    // epilogue: bias + GLU gate + store
#pragma unroll
    for (int r = 0; r < 4; r++) {
        int j = m0 + tty * 4 + r;
        float ba = bbase[j];
        float bg = bbase[j + Hv];
        float zs[8];
#pragma unroll
        for (int c = 0; c < 8; c++) {
            float av = acc_a[r][c] + ba;
            float gv = acc_g[r][c] + bg;
            zs[c] = av * (1.f / (1.f + expf(-gv)));
        }
        size_t out = ((size_t)(b * Hv + j)) * Lv + l0 + ttx * 8;
        *(float4*)&g_z[out]     = make_float4(zs[0], zs[1], zs[2], zs[3]);
        *(float4*)&g_z[out + 4] = make_float4(zs[4], zs[5], zs[6], zs[7]);
    }
}

// ---------------------------------------------------------------------------
// Residual + LayerNorm over H (per (b,l) column of the (B,H,L) layout).
// One thread per column.
// ---------------------------------------------------------------------------
__global__ void __launch_bounds__(256)
ln_kernel(const float* __restrict__ ln_g,
          const float* __restrict__ ln_b,
          int layer) {
    int idx = blockIdx.x * blockDim.x + threadIdx.x;   // 0..B*L
    int b = idx >> 12;
    int l = idx & (Lv - 1);
    const float* zc = g_z + ((size_t)b * Hv) * Lv + l;
    float* hc = g_h + ((size_t)b * Hv) * Lv + l;

    float s = 0.f, s2 = 0.f;
    for (int j = 0; j < Hv; j++) {
        float v = zc[(size_t)j * Lv] + hc[(size_t)j * Lv];
        s += v;
        s2 = fmaf(v, v, s2);
        hc[(size_t)j * Lv] = v;        // residual stored
    }
    float mu = s * (1.f / Hv);
    float var = s2 * (1.f / Hv) - mu * mu;
    float rstd = rsqrtf(var + LN_EPS);
    const float* lg = ln_g + layer * Hv;
    const float* lb = ln_b + layer * Hv;
    for (int j = 0; j < Hv; j++) {
        float v = (hc[(size_t)j * Lv] - mu) * rstd;
        hc[(size_t)j * Lv] = fmaf(v, lg[j], lb[j]);
    }
}

// ---------------------------------------------------------------------------
// Decoder: out[b] = sigmoid( sum_j dec2_w[j]*(sum_l h[b,j,l]*dec1_w[l] + dec1_b) + dec2_b )
// ---------------------------------------------------------------------------
__global__ void __launch_bounds__(256)
dec_kernel(const float* __restrict__ dec1_w,
           const float* __restrict__ dec1_b,
           const float* __restrict__ dec2_w,
           const float* __restrict__ dec2_b,
           float* __restrict__ out) {
    int b = blockIdx.x;
    int j = threadIdx.x;     // 256 threads, one per H row
    const float* hr = g_h + ((size_t)(b * Hv + j)) * Lv;
    float acc = 0.f;
    for (int l = 0; l < Lv; l += 4) {
        float4 hv = *(const float4*)&hr[l];
        float4 wv = *(const float4*)&dec1_w[l];
        acc = fmaf(hv.x, wv.x, acc);
        acc = fmaf(hv.y, wv.y, acc);
        acc = fmaf(hv.z, wv.z, acc);
        acc = fmaf(hv.w, wv.w, acc);
    }
    acc += dec1_b[0];
    acc *= dec2_w[j];

    __shared__ float red[256];
    red[j] = acc;
    __syncthreads();
#pragma unroll
    for (int off = 128; off > 0; off >>= 1) {
        if (j < off) red[j] += red[j + off];
        __syncthreads();
    }
    if (j == 0) {
        float y = red[0] + dec2_b[0];
        out[b] = 1.f / (1.f + expf(-y));
    }
}

// ---------------------------------------------------------------------------
extern "C" void kernel_launch(void* const* d_in, const int* in_sizes, int n_in,
                              void* d_out, int out_size) {
    const float* x          = (const float*)d_in[0];
    const float* enc_w      = (const float*)d_in[1];
    const float* enc_b      = (const float*)d_in[2];
    const float* log_dt     = (const float*)d_in[3];
    const float* log_A_real = (const float*)d_in[4];
    const float* A_imag     = (const float*)d_in[5];
    const float* C_re       = (const float*)d_in[6];
    const float* C_im       = (const float*)d_in[7];
    const float* Dp         = (const float*)d_in[8];
    const float* glu_w      = (const float*)d_in[9];
    const float* glu_b      = (const float*)d_in[10];
    const float* ln_g       = (const float*)d_in[11];
    const float* ln_b       = (const float*)d_in[12];
    const float* dec1_w     = (const float*)d_in[13];
    const float* dec1_b     = (const float*)d_in[14];
    const float* dec2_w     = (const float*)d_in[15];
    const float* dec2_b     = (const float*)d_in[16];
    float* out = (float*)d_out;

    // encoder: 33554432 elems / 4 per thread / 256 per block
    enc_kernel<<<32768, 256>>>(x, enc_w, enc_b);

    for (int layer = 0; layer < NLv; layer++) {
        scan_gelu_kernel<<<(Bv * Hv) / SEQ_PER_BLOCK, SCAN_THREADS>>>(
            log_dt, log_A_real, A_imag, C_re, C_im, Dp, layer);
        glu_kernel<<<dim3((Bv * Lv) / 128, Hv / 64), 256>>>(glu_w, glu_b, layer);
        ln_kernel<<<(Bv * Lv) / 256, 256>>>(ln_g, ln_b, layer);
    }

    dec_kernel<<<Bv, 256>>>(dec1_w, dec1_b, dec2_w, dec2_b, out);
}

// round 4
// speedup vs baseline: 1.0976x; 1.0976x over previous
#include <cuda_runtime.h>
#include <math.h>

// Problem constants
#define Bv 32
#define Lv 4096
#define Hv 256
#define NLv 4
#define N2v 32
#define LN_EPS 1e-5f

// Big scratch buffers in device global memory (allocation-free rule)
__device__ float g_h[(size_t)Bv * Hv * Lv];   // activations (B,H,L)
__device__ float g_g[(size_t)Bv * Hv * Lv];   // gelu(S4D output)
__device__ float g_z[(size_t)Bv * Hv * Lv];   // GLU output

// ---------------------------------------------------------------------------
// Packed f32x2 helpers (Blackwell sm_103a dual-rate fp32)
// ---------------------------------------------------------------------------
typedef unsigned long long u64p;

__device__ __forceinline__ u64p pk2(float lo, float hi) {
    u64p r; asm("mov.b64 %0, {%1,%2};" : "=l"(r) : "f"(lo), "f"(hi)); return r;
}
__device__ __forceinline__ void upk2(u64p v, float& lo, float& hi) {
    asm("mov.b64 {%0,%1}, %2;" : "=f"(lo), "=f"(hi) : "l"(v));
}
__device__ __forceinline__ u64p fma2(u64p a, u64p b, u64p c) {
    u64p d; asm("fma.rn.f32x2 %0, %1, %2, %3;" : "=l"(d) : "l"(a), "l"(b), "l"(c)); return d;
}
__device__ __forceinline__ u64p mul2(u64p a, u64p b) {
    u64p d; asm("mul.rn.f32x2 %0, %1, %2;" : "=l"(d) : "l"(a), "l"(b)); return d;
}

// ---------------------------------------------------------------------------
// Encoder: h[b,j,l] = x[b,l]*enc_w[j] + enc_b[j]   (CH=1)
// ---------------------------------------------------------------------------
__global__ void enc_kernel(const float* __restrict__ x,
                           const float* __restrict__ enc_w,
                           const float* __restrict__ enc_b) {
    size_t t = (size_t)blockIdx.x * blockDim.x + threadIdx.x;
    size_t idx4 = t * 4;
    int l = (int)(idx4 & (Lv - 1));
    int j = (int)((idx4 >> 12) & (Hv - 1));
    int b = (int)(idx4 >> 20);
    float w = enc_w[j];
    float bias = enc_b[j];
    const float4 xv = *(const float4*)&x[(size_t)b * Lv + l];
    float4 o;
    o.x = fmaf(xv.x, w, bias);
    o.y = fmaf(xv.y, w, bias);
    o.z = fmaf(xv.z, w, bias);
    o.w = fmaf(xv.w, w, bias);
    *(float4*)&g_h[idx4] = o;
}

// ---------------------------------------------------------------------------
// S4D scan + D skip + exact GELU.
// 4 threads per (b,h) sequence; 8 complex states per thread packed as 4
// f32x2 pairs (states are independent -> perfect SIMD over the pair).
// ---------------------------------------------------------------------------
#define SEQ_PER_BLOCK 32
#define SCAN_THREADS 128
#define CHUNK 128

__global__ void __launch_bounds__(SCAN_THREADS)
scan_gelu_kernel(const float* __restrict__ log_dt,
                 const float* __restrict__ log_A_real,
                 const float* __restrict__ A_imag,
                 const float* __restrict__ C_re,
                 const float* __restrict__ C_im,
                 const float* __restrict__ Dp,
                 int layer) {
    __shared__ float su[SEQ_PER_BLOCK][CHUNK + 1];
    __shared__ float sy[SEQ_PER_BLOCK][CHUNK + 1];

    const int tid = threadIdx.x;
    const int seq_local = tid >> 2;   // 0..31
    const int sub = tid & 3;          // 0..3 (state group)
    const int seq = blockIdx.x * SEQ_PER_BLOCK + seq_local;
    const int hh = seq & (Hv - 1);

    // Discretize: lambda = exp(dt*A), Ck = 2*C*(lambda-1)/A
    const int pb = (layer * Hv + hh) * N2v + sub * 8;
    float lrs[8], lis[8], ckrs[8], ckis[8];
    const float dt = expf(log_dt[layer * Hv + hh]);
#pragma unroll
    for (int k = 0; k < 8; k++) {
        float Ar = -expf(log_A_real[pb + k]);
        float Ai = A_imag[pb + k];
        float dAr = Ar * dt, dAi = Ai * dt;
        float e = expf(dAr);
        float lrr = e * cosf(dAi);
        float lii = e * sinf(dAi);
        lrs[k] = lrr; lis[k] = lii;
        float cr = C_re[pb + k], ci = C_im[pb + k];
        float nr = cr * (lrr - 1.f) - ci * lii;
        float ni = cr * lii + ci * (lrr - 1.f);
        float inv = 1.f / (Ar * Ar + Ai * Ai);
        ckrs[k] =  2.f * (nr * Ar + ni * Ai) * inv;
        ckis[k] = -2.f * (ni * Ar - nr * Ai) * inv;
    }
    // pack state pairs
    u64p lr2[4], li2[4], nli2[4], ckr2[4], cki2[4], sr2[4], si2[4];
#pragma unroll
    for (int p = 0; p < 4; p++) {
        lr2[p]  = pk2(lrs[2*p],  lrs[2*p+1]);
        li2[p]  = pk2(lis[2*p],  lis[2*p+1]);
        nli2[p] = pk2(-lis[2*p], -lis[2*p+1]);
        ckr2[p] = pk2(ckrs[2*p], ckrs[2*p+1]);
        cki2[p] = pk2(ckis[2*p], ckis[2*p+1]);
        sr2[p] = 0ull; si2[p] = 0ull;
    }
    const float Dh = Dp[layer * Hv + hh];
    const size_t base = (size_t)blockIdx.x * SEQ_PER_BLOCK * Lv;

    for (int c0 = 0; c0 < Lv; c0 += CHUNK) {
        __syncthreads();
#pragma unroll
        for (int it = 0; it < (SEQ_PER_BLOCK * CHUNK) / SCAN_THREADS; it++) {
            int i = tid + it * SCAN_THREADS;
            int s = i >> 7;
            int l = i & (CHUNK - 1);
            su[s][l] = g_h[base + (size_t)s * Lv + c0 + l];
        }
        __syncthreads();

        for (int l = 0; l < CHUNK; l++) {
            float u = su[seq_local][l];
            u64p u2 = pk2(u, u);
            u64p acc2 = 0ull;
#pragma unroll
            for (int p = 0; p < 4; p++) {
                u64p nr = fma2(lr2[p], sr2[p], u2);
                nr = fma2(nli2[p], si2[p], nr);
                u64p ni = fma2(li2[p], sr2[p], mul2(lr2[p], si2[p]));
                sr2[p] = nr; si2[p] = ni;
                acc2 = fma2(ckr2[p], nr, acc2);
                acc2 = fma2(cki2[p], ni, acc2);
            }
            float a0, a1; upk2(acc2, a0, a1);
            float acc = a0 + a1;
            acc += __shfl_xor_sync(0xffffffffu, acc, 1);
            acc += __shfl_xor_sync(0xffffffffu, acc, 2);
            if (sub == 0) {
                float y = fmaf(Dh, u, acc);
                sy[seq_local][l] = 0.5f * y * (1.f + erff(y * 0.70710678118654752f));
            }
        }
        __syncthreads();
#pragma unroll
        for (int it = 0; it < (SEQ_PER_BLOCK * CHUNK) / SCAN_THREADS; it++) {
            int i = tid + it * SCAN_THREADS;
            int s = i >> 7;
            int l = i & (CHUNK - 1);
            g_g[base + (size_t)s * Lv + c0 + l] = sy[s][l];
        }
    }
}

// ---------------------------------------------------------------------------
// GLU: Z[b,j,l] = a * sigmoid(g)
// Tiled GEMM, f32x2-packed accumulation: block = 64 row-pairs x 128 cols.
// 256 threads, each computes 4 row-pairs x 8 cols (4 packed col-pairs).
// ---------------------------------------------------------------------------
__global__ void __launch_bounds__(256)
glu_kernel(const float* __restrict__ glu_w,
           const float* __restrict__ glu_b,
           int layer) {
    __shared__ float sWa[16][68];
    __shared__ float sWg[16][68];
    __shared__ float sGt[16][132];   // row stride 528B = 66 x 8B, 8B-aligned

    const int tid = threadIdx.x;
    const int ttx = tid & 15;      // col group
    const int tty = tid >> 4;      // row group
    const int m0 = blockIdx.y * 64;
    const int n0 = blockIdx.x * 128;
    const int b = n0 >> 12;
    const int l0 = n0 & (Lv - 1);

    const float* wbase = glu_w + (size_t)layer * 2 * Hv * Hv;
    const float* bbase = glu_b + (size_t)layer * 2 * Hv;

    u64p acc_a[4][4], acc_g[4][4];
#pragma unroll
    for (int r = 0; r < 4; r++)
#pragma unroll
        for (int c = 0; c < 4; c++) { acc_a[r][c] = 0ull; acc_g[r][c] = 0ull; }

    for (int kc = 0; kc < Hv; kc += 16) {
        __syncthreads();
#pragma unroll
        for (int it = 0; it < 4; it++) {
            int i = tid + it * 256;
            int k = i & 15;
            int r = i >> 4;
            sWa[k][r] = wbase[(size_t)(m0 + r) * Hv + kc + k];
            sWg[k][r] = wbase[(size_t)(m0 + r + Hv) * Hv + kc + k];
        }
#pragma unroll
        for (int it = 0; it < 8; it++) {
            int i = tid + it * 256;
            int c = i & 127;
            int k = i >> 7;
            sGt[k][c] = g_g[((size_t)(b * Hv + kc + k)) * Lv + l0 + c];
        }
        __syncthreads();

#pragma unroll
        for (int k = 0; k < 16; k++) {
            const u64p* gp = (const u64p*)&sGt[k][ttx * 8];
            u64p g2[4];
#pragma unroll
            for (int c = 0; c < 4; c++) g2[c] = gp[c];
            float4 wa = *(const float4*)&sWa[k][tty * 4];
            float4 wg = *(const float4*)&sWg[k][tty * 4];
            u64p wa2[4], wg2[4];
            wa2[0] = pk2(wa.x, wa.x); wa2[1] = pk2(wa.y, wa.y);
            wa2[2] = pk2(wa.z, wa.z); wa2[3] = pk2(wa.w, wa.w);
            wg2[0] = pk2(wg.x, wg.x); wg2[1] = pk2(wg.y, wg.y);
            wg2[2] = pk2(wg.z, wg.z); wg2[3] = pk2(wg.w, wg.w);
#pragma unroll
            for (int r = 0; r < 4; r++)
#pragma unroll
                for (int c = 0; c < 4; c++) {
                    acc_a[r][c] = fma2(wa2[r], g2[c], acc_a[r][c]);
                    acc_g[r][c] = fma2(wg2[r], g2[c], acc_g[r][c]);
                }
        }
    }

    // epilogue: bias + GLU gate + store
#pragma unroll
    for (int r = 0; r < 4; r++) {
        int j = m0 + tty * 4 + r;
        float ba = bbase[j];
        float bg = bbase[j + Hv];
        float zs[8];
#pragma unroll
        for (int c = 0; c < 4; c++) {
            float a0, a1, gg0, gg1;
            upk2(acc_a[r][c], a0, a1);
            upk2(acc_g[r][c], gg0, gg1);
            float av0 = a0 + ba, av1 = a1 + ba;
            float gv0 = gg0 + bg, gv1 = gg1 + bg;
            zs[2*c]   = av0 * (1.f / (1.f + expf(-gv0)));
            zs[2*c+1] = av1 * (1.f / (1.f + expf(-gv1)));
        }
        size_t out = ((size_t)(b * Hv + j)) * Lv + l0 + ttx * 8;
        *(float4*)&g_z[out]     = make_float4(zs[0], zs[1], zs[2], zs[3]);
        *(float4*)&g_z[out + 4] = make_float4(zs[4], zs[5], zs[6], zs[7]);
    }
}

// ---------------------------------------------------------------------------
// Residual + LayerNorm over H. One thread per 4 adjacent (b,l) columns
// (float4 vectorized along l).
// ---------------------------------------------------------------------------
__global__ void __launch_bounds__(256)
ln_kernel(const float* __restrict__ ln_g,
          const float* __restrict__ ln_b,
          int layer) {
    int idx = blockIdx.x * blockDim.x + threadIdx.x;   // column-quad index
    int col0 = idx * 4;
    int b = col0 >> 12;
    int l = col0 & (Lv - 1);
    const float* zc = g_z + ((size_t)b * Hv) * Lv + l;
    float* hc = g_h + ((size_t)b * Hv) * Lv + l;

    float4 s = make_float4(0.f, 0.f, 0.f, 0.f);
    float4 s2 = make_float4(0.f, 0.f, 0.f, 0.f);
    for (int j = 0; j < Hv; j++) {
        float4 zv = *(const float4*)&zc[(size_t)j * Lv];
        float4 hv = *(const float4*)&hc[(size_t)j * Lv];
        float4 v = make_float4(zv.x + hv.x, zv.y + hv.y, zv.z + hv.z, zv.w + hv.w);
        s.x += v.x; s.y += v.y; s.z += v.z; s.w += v.w;
        s2.x = fmaf(v.x, v.x, s2.x); s2.y = fmaf(v.y, v.y, s2.y);
        s2.z = fmaf(v.z, v.z, s2.z); s2.w = fmaf(v.w, v.w, s2.w);
        *(float4*)&hc[(size_t)j * Lv] = v;
    }
    const float inv = 1.f / Hv;
    float4 mu = make_float4(s.x * inv, s.y * inv, s.z * inv, s.w * inv);
    float4 rstd;
    rstd.x = rsqrtf(s2.x * inv - mu.x * mu.x + LN_EPS);
    rstd.y = rsqrtf(s2.y * inv - mu.y * mu.y + LN_EPS);
    rstd.z = rsqrtf(s2.z * inv - mu.z * mu.z + LN_EPS);
    rstd.w = rsqrtf(s2.w * inv - mu.w * mu.w + LN_EPS);
    const float* lg = ln_g + layer * Hv;
    const float* lb = ln_b + layer * Hv;
    for (int j = 0; j < Hv; j++) {
        float g = lg[j], bb = lb[j];
        float4 v = *(const float4*)&hc[(size_t)j * Lv];
        v.x = fmaf((v.x - mu.x) * rstd.x, g, bb);
        v.y = fmaf((v.y - mu.y) * rstd.y, g, bb);
        v.z = fmaf((v.z - mu.z) * rstd.z, g, bb);
        v.w = fmaf((v.w - mu.w) * rstd.w, g, bb);
        *(float4*)&hc[(size_t)j * Lv] = v;
    }
}

// ---------------------------------------------------------------------------
// Decoder
// ---------------------------------------------------------------------------
__global__ void __launch_bounds__(256)
dec_kernel(const float* __restrict__ dec1_w,
           const float* __restrict__ dec1_b,
           const float* __restrict__ dec2_w,
           const float* __restrict__ dec2_b,
           float* __restrict__ out) {
    int b = blockIdx.x;
    int j = threadIdx.x;
    const float* hr = g_h + ((size_t)(b * Hv + j)) * Lv;
    float acc = 0.f;
    for (int l = 0; l < Lv; l += 4) {
        float4 hv = *(const float4*)&hr[l];
        float4 wv = *(const float4*)&dec1_w[l];
        acc = fmaf(hv.x, wv.x, acc);
        acc = fmaf(hv.y, wv.y, acc);
        acc = fmaf(hv.z, wv.z, acc);
        acc = fmaf(hv.w, wv.w, acc);
    }
    acc += dec1_b[0];
    acc *= dec2_w[j];

    __shared__ float red[256];
    red[j] = acc;
    __syncthreads();
#pragma unroll
    for (int off = 128; off > 0; off >>= 1) {
        if (j < off) red[j] += red[j + off];
        __syncthreads();
    }
    if (j == 0) {
        float y = red[0] + dec2_b[0];
        out[b] = 1.f / (1.f + expf(-y));
    }
}

// ---------------------------------------------------------------------------
extern "C" void kernel_launch(void* const* d_in, const int* in_sizes, int n_in,
                              void* d_out, int out_size) {
    const float* x          = (const float*)d_in[0];
    const float* enc_w      = (const float*)d_in[1];
    const float* enc_b      = (const float*)d_in[2];
    const float* log_dt     = (const float*)d_in[3];
    const float* log_A_real = (const float*)d_in[4];
    const float* A_imag     = (const float*)d_in[5];
    const float* C_re       = (const float*)d_in[6];
    const float* C_im       = (const float*)d_in[7];
    const float* Dp         = (const float*)d_in[8];
    const float* glu_w      = (const float*)d_in[9];
    const float* glu_b      = (const float*)d_in[10];
    const float* ln_g       = (const float*)d_in[11];
    const float* ln_b       = (const float*)d_in[12];
    const float* dec1_w     = (const float*)d_in[13];
    const float* dec1_b     = (const float*)d_in[14];
    const float* dec2_w     = (const float*)d_in[15];
    const float* dec2_b     = (const float*)d_in[16];
    float* out = (float*)d_out;

    enc_kernel<<<32768, 256>>>(x, enc_w, enc_b);

    for (int layer = 0; layer < NLv; layer++) {
        scan_gelu_kernel<<<(Bv * Hv) / SEQ_PER_BLOCK, SCAN_THREADS>>>(
            log_dt, log_A_real, A_imag, C_re, C_im, Dp, layer);
        glu_kernel<<<dim3((Bv * Lv) / 128, Hv / 64), 256>>>(glu_w, glu_b, layer);
        ln_kernel<<<(Bv * Lv) / (256 * 4), 256>>>(ln_g, ln_b, layer);
    }

    dec_kernel<<<Bv, 256>>>(dec1_w, dec1_b, dec2_w, dec2_b, out);
}

// round 6
// speedup vs baseline: 1.4974x; 1.3642x over previous
#include <cuda_runtime.h>
#include <cuda_bf16.h>
#include <math.h>

// Problem constants
#define Bv 32
#define Lv 4096
#define Hv 256
#define NLv 4
#define N2v 32
#define LN_EPS 1e-5f

// Scratch (allocation-free rule: device globals)
__device__ float    g_h[(size_t)Bv * Hv * Lv];    // activations (B,H,L) fp32
__device__ unsigned g_gpk[(size_t)Bv * Hv * Lv];  // gelu output, packed bf16 hi|lo<<16
__device__ float    g_z[(size_t)Bv * Hv * Lv];    // GLU output fp32
__device__ unsigned g_wpk[512 * 256];             // packed W hi/lo for current layer

// ---------------------------------------------------------------------------
// f32x2 helpers (kept for the scan kernel)
// ---------------------------------------------------------------------------
typedef unsigned long long u64p;
__device__ __forceinline__ u64p pk2(float lo, float hi) {
    u64p r; asm("mov.b64 %0, {%1,%2};" : "=l"(r) : "f"(lo), "f"(hi)); return r;
}
__device__ __forceinline__ void upk2(u64p v, float& lo, float& hi) {
    asm("mov.b64 {%0,%1}, %2;" : "=f"(lo), "=f"(hi) : "l"(v));
}
__device__ __forceinline__ u64p fma2(u64p a, u64p b, u64p c) {
    u64p d; asm("fma.rn.f32x2 %0, %1, %2, %3;" : "=l"(d) : "l"(a), "l"(b), "l"(c)); return d;
}
__device__ __forceinline__ u64p mul2(u64p a, u64p b) {
    u64p d; asm("mul.rn.f32x2 %0, %1, %2;" : "=l"(d) : "l"(a), "l"(b)); return d;
}

// bf16 split pack: hi = bf16(x), lo = bf16(x - hi), packed hi | lo<<16
__device__ __forceinline__ unsigned bf16split(float x) {
    __nv_bfloat16 h = __float2bfloat16(x);
    float hf = __bfloat162float(h);
    __nv_bfloat16 l = __float2bfloat16(x - hf);
    return (unsigned)__bfloat16_as_ushort(h) | ((unsigned)__bfloat16_as_ushort(l) << 16);
}

// ---------------------------------------------------------------------------
// Encoder
// ---------------------------------------------------------------------------
__global__ void enc_kernel(const float* __restrict__ x,
                           const float* __restrict__ enc_w,
                           const float* __restrict__ enc_b) {
    size_t t = (size_t)blockIdx.x * blockDim.x + threadIdx.x;
    size_t idx4 = t * 4;
    int l = (int)(idx4 & (Lv - 1));
    int j = (int)((idx4 >> 12) & (Hv - 1));
    int b = (int)(idx4 >> 20);
    float w = enc_w[j];
    float bias = enc_b[j];
    const float4 xv = *(const float4*)&x[(size_t)b * Lv + l];
    float4 o;
    o.x = fmaf(xv.x, w, bias);
    o.y = fmaf(xv.y, w, bias);
    o.z = fmaf(xv.z, w, bias);
    o.w = fmaf(xv.w, w, bias);
    *(float4*)&g_h[idx4] = o;
}

// ---------------------------------------------------------------------------
// W conversion: pack glu_w layer into bf16 hi/lo u32
// ---------------------------------------------------------------------------
__global__ void wconv_kernel(const float* __restrict__ glu_w, int layer) {
    int i = blockIdx.x * 256 + threadIdx.x;   // 0..131071
    g_wpk[i] = bf16split(glu_w[(size_t)layer * 512 * 256 + i]);
}

// ---------------------------------------------------------------------------
// S4D scan + D skip + exact GELU (f32x2 state pairs), emits packed bf16 split
// ---------------------------------------------------------------------------
#define SEQ_PER_BLOCK 32
#define SCAN_THREADS 128
#define CHUNK 128

__global__ void __launch_bounds__(SCAN_THREADS)
scan_gelu_kernel(const float* __restrict__ log_dt,
                 const float* __restrict__ log_A_real,
                 const float* __restrict__ A_imag,
                 const float* __restrict__ C_re,
                 const float* __restrict__ C_im,
                 const float* __restrict__ Dp,
                 int layer) {
    __shared__ float su[SEQ_PER_BLOCK][CHUNK + 1];
    __shared__ float sy[SEQ_PER_BLOCK][CHUNK + 1];

    const int tid = threadIdx.x;
    const int seq_local = tid >> 2;
    const int sub = tid & 3;
    const int seq = blockIdx.x * SEQ_PER_BLOCK + seq_local;
    const int hh = seq & (Hv - 1);

    const int pb = (layer * Hv + hh) * N2v + sub * 8;
    float lrs[8], lis[8], ckrs[8], ckis[8];
    const float dt = expf(log_dt[layer * Hv + hh]);
#pragma unroll
    for (int k = 0; k < 8; k++) {
        float Ar = -expf(log_A_real[pb + k]);
        float Ai = A_imag[pb + k];
        float dAr = Ar * dt, dAi = Ai * dt;
        float e = expf(dAr);
        float lrr = e * cosf(dAi);
        float lii = e * sinf(dAi);
        lrs[k] = lrr; lis[k] = lii;
        float cr = C_re[pb + k], ci = C_im[pb + k];
        float nr = cr * (lrr - 1.f) - ci * lii;
        float ni = cr * lii + ci * (lrr - 1.f);
        float inv = 1.f / (Ar * Ar + Ai * Ai);
        ckrs[k] =  2.f * (nr * Ar + ni * Ai) * inv;
        ckis[k] = -2.f * (ni * Ar - nr * Ai) * inv;
    }
    u64p lr2[4], li2[4], nli2[4], ckr2[4], cki2[4], sr2[4], si2[4];
#pragma unroll
    for (int p = 0; p < 4; p++) {
        lr2[p]  = pk2(lrs[2*p],  lrs[2*p+1]);
        li2[p]  = pk2(lis[2*p],  lis[2*p+1]);
        nli2[p] = pk2(-lis[2*p], -lis[2*p+1]);
        ckr2[p] = pk2(ckrs[2*p], ckrs[2*p+1]);
        cki2[p] = pk2(ckis[2*p], ckis[2*p+1]);
        sr2[p] = 0ull; si2[p] = 0ull;
    }
    const float Dh = Dp[layer * Hv + hh];
    const size_t base = (size_t)blockIdx.x * SEQ_PER_BLOCK * Lv;

    for (int c0 = 0; c0 < Lv; c0 += CHUNK) {
        __syncthreads();
#pragma unroll
        for (int it = 0; it < (SEQ_PER_BLOCK * CHUNK) / SCAN_THREADS; it++) {
            int i = tid + it * SCAN_THREADS;
            int s = i >> 7;
            int l = i & (CHUNK - 1);
            su[s][l] = g_h[base + (size_t)s * Lv + c0 + l];
        }
        __syncthreads();

        for (int l = 0; l < CHUNK; l++) {
            float u = su[seq_local][l];
            u64p u2 = pk2(u, u);
            u64p acc2 = 0ull;
#pragma unroll
            for (int p = 0; p < 4; p++) {
                u64p nr = fma2(lr2[p], sr2[p], u2);
                nr = fma2(nli2[p], si2[p], nr);
                u64p ni = fma2(li2[p], sr2[p], mul2(lr2[p], si2[p]));
                sr2[p] = nr; si2[p] = ni;
                acc2 = fma2(ckr2[p], nr, acc2);
                acc2 = fma2(cki2[p], ni, acc2);
            }
            float a0, a1; upk2(acc2, a0, a1);
            float acc = a0 + a1;
            acc += __shfl_xor_sync(0xffffffffu, acc, 1);
            acc += __shfl_xor_sync(0xffffffffu, acc, 2);
            if (sub == 0) {
                float y = fmaf(Dh, u, acc);
                sy[seq_local][l] = 0.5f * y * (1.f + erff(y * 0.70710678118654752f));
            }
        }
        __syncthreads();
#pragma unroll
        for (int it = 0; it < (SEQ_PER_BLOCK * CHUNK) / SCAN_THREADS; it++) {
            int i = tid + it * SCAN_THREADS;
            int s = i >> 7;
            int l = i & (CHUNK - 1);
            g_gpk[base + (size_t)s * Lv + c0 + l] = bf16split(sy[s][l]);
        }
    }
}

// ---------------------------------------------------------------------------
// GLU GEMM on tensor cores: mma.sync.m16n8k16 bf16, hi/lo split (3 products).
// Block: 256 thr = 8 warps (2 warp_m x 4 warp_n).
// Output tile: 64 'a'-rows (j0..j0+63) + 64 'g'-rows (j0+256..), 128 cols.
// Each warp: 32 j-rows x 32 cols of both a and g.
// ---------------------------------------------------------------------------
#define KC 32

__device__ __forceinline__ void mma16816(float* c, const unsigned* a, const unsigned* b) {
    asm volatile(
        "mma.sync.aligned.m16n8k16.row.col.f32.bf16.bf16.f32 "
        "{%0,%1,%2,%3}, {%4,%5,%6,%7}, {%8,%9}, {%0,%1,%2,%3};"
        : "+f"(c[0]), "+f"(c[1]), "+f"(c[2]), "+f"(c[3])
        : "r"(a[0]), "r"(a[1]), "r"(a[2]), "r"(a[3]), "r"(b[0]), "r"(b[1]));
}

__global__ void __launch_bounds__(256)
glu_mma_kernel(const float* __restrict__ glu_b, int layer) {
    __shared__ unsigned short sWhi[128][KC + 4];
    __shared__ unsigned short sWlo[128][KC + 4];
    __shared__ unsigned short sGhi[128][KC + 4];   // transposed: [col l][k]
    __shared__ unsigned short sGlo[128][KC + 4];

    const int tid = threadIdx.x;
    const int warp = tid >> 5, lane = tid & 31;
    const int gid = lane >> 2, tig = lane & 3;
    const int warp_m = warp & 1, warp_n = warp >> 1;
    const int j0 = blockIdx.y * 64;
    const int n0 = blockIdx.x * 128;
    const int b = n0 >> 12, l0 = n0 & (Lv - 1);

    float acc[4][4][4];   // [a-m0, a-m1, g-m0, g-m1][ni][c0..3]
#pragma unroll
    for (int t = 0; t < 4; t++)
#pragma unroll
        for (int n = 0; n < 4; n++)
#pragma unroll
            for (int c = 0; c < 4; c++) acc[t][n][c] = 0.f;

    for (int kc = 0; kc < Hv; kc += KC) {
        __syncthreads();
        // W tile: rows 0-63 -> a rows j0+r ; rows 64-127 -> g rows 256+j0+(r-64)
#pragma unroll
        for (int i = tid; i < 128 * KC; i += 256) {
            int row = i >> 5;
            int k = i & (KC - 1);
            int grow = (row < 64) ? (j0 + row) : (256 + j0 + row - 64);
            unsigned v = g_wpk[grow * Hv + kc + k];
            sWhi[row][k] = (unsigned short)(v & 0xffffu);
            sWlo[row][k] = (unsigned short)(v >> 16);
        }
        // G tile, transposed into [l][k]
#pragma unroll
        for (int i = tid; i < KC * 128; i += 256) {
            int h = i >> 7;
            int l = i & 127;
            unsigned v = g_gpk[((size_t)(b * Hv + kc + h)) * Lv + l0 + l];
            sGhi[l][h] = (unsigned short)(v & 0xffffu);
            sGlo[l][h] = (unsigned short)(v >> 16);
        }
        __syncthreads();

#pragma unroll
        for (int ks = 0; ks < KC / 16; ks++) {
            const int kb = ks * 16;
            unsigned ahi[4][4], alo[4][4];
#pragma unroll
            for (int t4 = 0; t4 < 4; t4++) {
                int rowb = ((t4 >> 1) ? 64 : 0) + 32 * warp_m + 16 * (t4 & 1) + gid;
                ahi[t4][0] = *(const unsigned*)&sWhi[rowb][kb + 2 * tig];
                ahi[t4][1] = *(const unsigned*)&sWhi[rowb + 8][kb + 2 * tig];
                ahi[t4][2] = *(const unsigned*)&sWhi[rowb][kb + 2 * tig + 8];
                ahi[t4][3] = *(const unsigned*)&sWhi[rowb + 8][kb + 2 * tig + 8];
                alo[t4][0] = *(const unsigned*)&sWlo[rowb][kb + 2 * tig];
                alo[t4][1] = *(const unsigned*)&sWlo[rowb + 8][kb + 2 * tig];
                alo[t4][2] = *(const unsigned*)&sWlo[rowb][kb + 2 * tig + 8];
                alo[t4][3] = *(const unsigned*)&sWlo[rowb + 8][kb + 2 * tig + 8];
            }
            unsigned bhi[4][2], blo[4][2];
#pragma unroll
            for (int ni = 0; ni < 4; ni++) {
                int col = 32 * warp_n + 8 * ni + gid;
                bhi[ni][0] = *(const unsigned*)&sGhi[col][kb + 2 * tig];
                bhi[ni][1] = *(const unsigned*)&sGhi[col][kb + 2 * tig + 8];
                blo[ni][0] = *(const unsigned*)&sGlo[col][kb + 2 * tig];
                blo[ni][1] = *(const unsigned*)&sGlo[col][kb + 2 * tig + 8];
            }
#pragma unroll
            for (int t4 = 0; t4 < 4; t4++)
#pragma unroll
                for (int ni = 0; ni < 4; ni++) {
                    mma16816(acc[t4][ni], ahi[t4], bhi[ni]);
                    mma16816(acc[t4][ni], ahi[t4], blo[ni]);
                    mma16816(acc[t4][ni], alo[t4], bhi[ni]);
                }
        }
    }

    // epilogue: bias + GLU gate + store fp32
    const float* bbase = glu_b + (size_t)layer * 512;
#pragma unroll
    for (int mi = 0; mi < 2; mi++) {
        int r0 = j0 + 32 * warp_m + 16 * mi + gid;
        float ba0 = bbase[r0],       ba1 = bbase[r0 + 8];
        float bg0 = bbase[r0 + 256], bg1 = bbase[r0 + 264];
#pragma unroll
        for (int ni = 0; ni < 4; ni++) {
            int col = n0 + 32 * warp_n + 8 * ni + 2 * tig;
            int lcol = col & (Lv - 1);
            float a0 = acc[mi][ni][0] + ba0, a1 = acc[mi][ni][1] + ba0;
            float a2 = acc[mi][ni][2] + ba1, a3 = acc[mi][ni][3] + ba1;
            float q0 = acc[mi + 2][ni][0] + bg0, q1 = acc[mi + 2][ni][1] + bg0;
            float q2 = acc[mi + 2][ni][2] + bg1, q3 = acc[mi + 2][ni][3] + bg1;
            float z0 = a0 * (1.f / (1.f + expf(-q0)));
            float z1 = a1 * (1.f / (1.f + expf(-q1)));
            float z2 = a2 * (1.f / (1.f + expf(-q2)));
            float z3 = a3 * (1.f / (1.f + expf(-q3)));
            *(float2*)&g_z[((size_t)(b * Hv + r0)) * Lv + lcol]     = make_float2(z0, z1);
            *(float2*)&g_z[((size_t)(b * Hv + r0 + 8)) * Lv + lcol] = make_float2(z2, z3);
        }
    }
}

// ---------------------------------------------------------------------------
// Residual + LayerNorm, single-pass smem tile: block per 32 (b,l) columns.
// ---------------------------------------------------------------------------
__global__ void __launch_bounds__(256)
ln_kernel(const float* __restrict__ ln_g,
          const float* __restrict__ ln_b,
          int layer) {
    __shared__ float sv[256][33];
    __shared__ float red[2][8][32];
    __shared__ float smu[32], srs[32];

    const int tid = threadIdx.x;
    const int c = tid & 31, hg = tid >> 5;
    const int col0 = blockIdx.x * 32;
    const int b = col0 >> 12;
    const int l0 = col0 & (Lv - 1);

    float s = 0.f, s2 = 0.f;
#pragma unroll 8
    for (int i = 0; i < 32; i++) {
        int h = hg * 32 + i;
        size_t idx = ((size_t)(b * Hv + h)) * Lv + l0 + c;
        float v = g_z[idx] + g_h[idx];
        sv[h][c] = v;
        s += v;
        s2 = fmaf(v, v, s2);
    }
    red[0][hg][c] = s;
    red[1][hg][c] = s2;
    __syncthreads();
    if (hg == 0) {
        float ts = 0.f, ts2 = 0.f;
#pragma unroll
        for (int g = 0; g < 8; g++) { ts += red[0][g][c]; ts2 += red[1][g][c]; }
        float mu = ts * (1.f / Hv);
        smu[c] = mu;
        srs[c] = rsqrtf(ts2 * (1.f / Hv) - mu * mu + LN_EPS);
    }
    __syncthreads();
    const float mu = smu[c], rs = srs[c];
    const float* lg = ln_g + layer * Hv;
    const float* lb = ln_b + layer * Hv;
#pragma unroll 8
    for (int i = 0; i < 32; i++) {
        int h = hg * 32 + i;
        float v = (sv[h][c] - mu) * rs;
        g_h[((size_t)(b * Hv + h)) * Lv + l0 + c] = fmaf(v, lg[h], lb[h]);
    }
}

// ---------------------------------------------------------------------------
// Decoder
// ---------------------------------------------------------------------------
__global__ void __launch_bounds__(256)
dec_kernel(const float* __restrict__ dec1_w,
           const float* __restrict__ dec1_b,
           const float* __restrict__ dec2_w,
           const float* __restrict__ dec2_b,
           float* __restrict__ out) {
    int b = blockIdx.x;
    int j = threadIdx.x;
    const float* hr = g_h + ((size_t)(b * Hv + j)) * Lv;
    float acc = 0.f;
    for (int l = 0; l < Lv; l += 4) {
        float4 hv = *(const float4*)&hr[l];
        float4 wv = *(const float4*)&dec1_w[l];
        acc = fmaf(hv.x, wv.x, acc);
        acc = fmaf(hv.y, wv.y, acc);
        acc = fmaf(hv.z, wv.z, acc);
        acc = fmaf(hv.w, wv.w, acc);
    }
    acc += dec1_b[0];
    acc *= dec2_w[j];

    __shared__ float red[256];
    red[j] = acc;
    __syncthreads();
#pragma unroll
    for (int off = 128; off > 0; off >>= 1) {
        if (j < off) red[j] += red[j + off];
        __syncthreads();
    }
    if (j == 0) {
        float y = red[0] + dec2_b[0];
        out[b] = 1.f / (1.f + expf(-y));
    }
}

// ---------------------------------------------------------------------------
extern "C" void kernel_launch(void* const* d_in, const int* in_sizes, int n_in,
                              void* d_out, int out_size) {
    const float* x          = (const float*)d_in[0];
    const float* enc_w      = (const float*)d_in[1];
    const float* enc_b      = (const float*)d_in[2];
    const float* log_dt     = (const float*)d_in[3];
    const float* log_A_real = (const float*)d_in[4];
    const float* A_imag     = (const float*)d_in[5];
    const float* C_re       = (const float*)d_in[6];
    const float* C_im       = (const float*)d_in[7];
    const float* Dp         = (const float*)d_in[8];
    const float* glu_w      = (const float*)d_in[9];
    const float* glu_b      = (const float*)d_in[10];
    const float* ln_g       = (const float*)d_in[11];
    const float* ln_b       = (const float*)d_in[12];
    const float* dec1_w     = (const float*)d_in[13];
    const float* dec1_b     = (const float*)d_in[14];
    const float* dec2_w     = (const float*)d_in[15];
    const float* dec2_b     = (const float*)d_in[16];
    float* out = (float*)d_out;

    enc_kernel<<<32768, 256>>>(x, enc_w, enc_b);

    for (int layer = 0; layer < NLv; layer++) {
        wconv_kernel<<<512, 256>>>(glu_w, layer);
        scan_gelu_kernel<<<(Bv * Hv) / SEQ_PER_BLOCK, SCAN_THREADS>>>(
            log_dt, log_A_real, A_imag, C_re, C_im, Dp, layer);
        glu_mma_kernel<<<dim3((Bv * Lv) / 128, Hv / 64), 256>>>(glu_b, layer);
        ln_kernel<<<(Bv * Lv) / 32, 256>>>(ln_g, ln_b, layer);
    }

    dec_kernel<<<Bv, 256>>>(dec1_w, dec1_b, dec2_w, dec2_b, out);
}

// round 10
// speedup vs baseline: 1.7656x; 1.1791x over previous
#include <cuda_runtime.h>
#include <cuda_bf16.h>
#include <math.h>

// Problem constants
#define Bv 32
#define Lv 4096
#define Hv 256
#define NLv 4
#define N2v 32
#define LN_EPS 1e-5f

// Scratch (allocation-free rule: device globals)
__device__ float    g_h[(size_t)Bv * Hv * Lv];    // activations (B,H,L) fp32
__device__ unsigned g_gpk[(size_t)Bv * Hv * Lv];  // gelu output, packed bf16 hi|lo<<16
__device__ float    g_z[(size_t)Bv * Hv * Lv];    // GLU output fp32
__device__ unsigned g_wpk[NLv * 512 * 256];       // packed W hi/lo, all layers

// ---------------------------------------------------------------------------
// f32x2 helpers
// ---------------------------------------------------------------------------
typedef unsigned long long u64p;
__device__ __forceinline__ u64p pk2(float lo, float hi) {
    u64p r; asm("mov.b64 %0, {%1,%2};" : "=l"(r) : "f"(lo), "f"(hi)); return r;
}
__device__ __forceinline__ void upk2(u64p v, float& lo, float& hi) {
    asm("mov.b64 {%0,%1}, %2;" : "=f"(lo), "=f"(hi) : "l"(v));
}
__device__ __forceinline__ u64p fma2(u64p a, u64p b, u64p c) {
    u64p d; asm("fma.rn.f32x2 %0, %1, %2, %3;" : "=l"(d) : "l"(a), "l"(b), "l"(c)); return d;
}
__device__ __forceinline__ u64p mul2(u64p a, u64p b) {
    u64p d; asm("mul.rn.f32x2 %0, %1, %2;" : "=l"(d) : "l"(a), "l"(b)); return d;
}

// bf16 split pack: hi = bf16(x), lo = bf16(x - hi), packed hi | lo<<16
__device__ __forceinline__ unsigned bf16split(float x) {
    __nv_bfloat16 h = __float2bfloat16(x);
    float hf = __bfloat162float(h);
    __nv_bfloat16 l = __float2bfloat16(x - hf);
    return (unsigned)__bfloat16_as_ushort(h) | ((unsigned)__bfloat16_as_ushort(l) << 16);
}

__device__ __forceinline__ void ldsm4(unsigned& r0, unsigned& r1, unsigned& r2, unsigned& r3,
                                      const void* p) {
    unsigned a = (unsigned)__cvta_generic_to_shared(p);
    asm volatile("ldmatrix.sync.aligned.m8n8.x4.shared.b16 {%0,%1,%2,%3}, [%4];"
                 : "=r"(r0), "=r"(r1), "=r"(r2), "=r"(r3) : "r"(a));
}

// ---------------------------------------------------------------------------
// Encoder
// ---------------------------------------------------------------------------
__global__ void enc_kernel(const float* __restrict__ x,
                           const float* __restrict__ enc_w,
                           const float* __restrict__ enc_b) {
    size_t t = (size_t)blockIdx.x * blockDim.x + threadIdx.x;
    size_t idx4 = t * 4;
    int l = (int)(idx4 & (Lv - 1));
    int j = (int)((idx4 >> 12) & (Hv - 1));
    int b = (int)(idx4 >> 20);
    float w = enc_w[j];
    float bias = enc_b[j];
    const float4 xv = *(const float4*)&x[(size_t)b * Lv + l];
    float4 o;
    o.x = fmaf(xv.x, w, bias);
    o.y = fmaf(xv.y, w, bias);
    o.z = fmaf(xv.z, w, bias);
    o.w = fmaf(xv.w, w, bias);
    *(float4*)&g_h[idx4] = o;
}

// ---------------------------------------------------------------------------
// W conversion: pack all layers' glu_w into bf16 hi/lo u32 (one launch)
// ---------------------------------------------------------------------------
__global__ void wconv_kernel(const float* __restrict__ glu_w) {
    int i = blockIdx.x * 256 + threadIdx.x;
    g_wpk[i] = bf16split(glu_w[i]);
}

// ---------------------------------------------------------------------------
// Segment-parallel S4D scan + D skip + GELU + bf16 pack.
// One block per (b,h) sequence: 256 threads = 64 segments x 4 state-subs.
// Phase1: zero-init segment scans -> boundary states E.
// Phase2: warp0 composes E with lambda^64 (6 complex squarings) -> s_in.
// Phase3: rescan with s_in, emit pre-activation y.
// Phase4: coalesced GELU + pack + store.
// ---------------------------------------------------------------------------
#define NSEG 64
#define SGT 64

__global__ void __launch_bounds__(256)
scan_gelu_kernel(const float* __restrict__ log_dt,
                 const float* __restrict__ log_A_real,
                 const float* __restrict__ A_imag,
                 const float* __restrict__ C_re,
                 const float* __restrict__ C_im,
                 const float* __restrict__ Dp,
                 int layer) {
    __shared__ float su[NSEG * 65];
    __shared__ float sy[NSEG * 65];
    __shared__ float2 sE[NSEG][33];
    __shared__ float4 sCoef[32];   // (lr, li, ckr, cki) per state

    const int tid = threadIdx.x;
    const int sub = tid & 3;
    const int seg = tid >> 2;
    const int seq = blockIdx.x;          // 0..8191
    const int hh = seq & (Hv - 1);
    const size_t base = (size_t)seq * Lv;

    // stage u into smem (padded [seg][65] layout), coalesced float4 reads
#pragma unroll
    for (int it = 0; it < 4; it++) {
        int i = it * 256 + tid;              // 0..1023 float4s
        float4 v = *(const float4*)&g_h[base + (size_t)i * 4];
        int sg = i >> 4;
        int l = (i & 15) * 4;
        float* p = &su[sg * 65 + l];
        p[0] = v.x; p[1] = v.y; p[2] = v.z; p[3] = v.w;
    }

    // per-state coefficients (32 threads, shared)
    if (tid < 32) {
        int n = tid;
        const int pb = (layer * Hv + hh) * N2v + n;
        float dt = expf(log_dt[layer * Hv + hh]);
        float Ar = -expf(log_A_real[pb]);
        float Ai = A_imag[pb];
        float dAr = Ar * dt, dAi = Ai * dt;
        float e = expf(dAr);
        float lrr = e * cosf(dAi);
        float lii = e * sinf(dAi);
        float cr = C_re[pb], ci = C_im[pb];
        float nr = cr * (lrr - 1.f) - ci * lii;
        float ni = cr * lii + ci * (lrr - 1.f);
        float inv = 1.f / (Ar * Ar + Ai * Ai);
        float ckr =  2.f * (nr * Ar + ni * Ai) * inv;
        float cki = -2.f * (ni * Ar - nr * Ai) * inv;
        sCoef[n] = make_float4(lrr, lii, ckr, cki);
    }
    __syncthreads();

    // load per-thread packed coefficients (8 states = 4 pairs)
    u64p lr2[4], li2[4], nli2[4], ckr2[4], cki2[4], sr2[4], si2[4];
#pragma unroll
    for (int p = 0; p < 4; p++) {
        float4 c0 = sCoef[sub * 8 + 2 * p];
        float4 c1 = sCoef[sub * 8 + 2 * p + 1];
        lr2[p]  = pk2(c0.x, c1.x);
        li2[p]  = pk2(c0.y, c1.y);
        nli2[p] = pk2(-c0.y, -c1.y);
        ckr2[p] = pk2(c0.z, c1.z);
        cki2[p] = pk2(c0.w, c1.w);
        sr2[p] = 0ull; si2[p] = 0ull;
    }
    const float Dh = Dp[layer * Hv + hh];
    const float* sus = &su[seg * 65];

    // phase 1: zero-init segment scan (state update only)
#pragma unroll 4
    for (int l = 0; l < SGT; l++) {
        float u = sus[l];
        u64p u2 = pk2(u, u);
#pragma unroll
        for (int p = 0; p < 4; p++) {
            u64p nr = fma2(lr2[p], sr2[p], u2);
            nr = fma2(nli2[p], si2[p], nr);
            u64p ni = fma2(li2[p], sr2[p], mul2(lr2[p], si2[p]));
            sr2[p] = nr; si2[p] = ni;
        }
    }
#pragma unroll
    for (int p = 0; p < 4; p++) {
        float r0, r1, i0, i1;
        upk2(sr2[p], r0, r1);
        upk2(si2[p], i0, i1);
        sE[seg][sub * 8 + 2 * p]     = make_float2(r0, i0);
        sE[seg][sub * 8 + 2 * p + 1] = make_float2(r1, i1);
    }
    __syncthreads();

    // phase 2: compose boundary states (one thread per state)
    if (tid < 32) {
        float4 c = sCoef[tid];
        float tr = c.x, ti = c.y;   // lambda
#pragma unroll
        for (int q = 0; q < 6; q++) {   // lambda^64 by squaring
            float nr = tr * tr - ti * ti;
            float ni = 2.f * tr * ti;
            tr = nr; ti = ni;
        }
        float sr = 0.f, si = 0.f;
        for (int cseg = 0; cseg < NSEG; cseg++) {
            float2 e = sE[cseg][tid];
            sE[cseg][tid] = make_float2(sr, si);   // s_in for this segment
            float nr = tr * sr - ti * si + e.x;
            float ni = tr * si + ti * sr + e.y;
            sr = nr; si = ni;
        }
    }
    __syncthreads();

    // phase 3: rescan with correct initial state, emit pre-activation y
#pragma unroll
    for (int p = 0; p < 4; p++) {
        float2 a = sE[seg][sub * 8 + 2 * p];
        float2 b2 = sE[seg][sub * 8 + 2 * p + 1];
        sr2[p] = pk2(a.x, b2.x);
        si2[p] = pk2(a.y, b2.y);
    }
    float* sys = &sy[seg * 65];
#pragma unroll 4
    for (int l = 0; l < SGT; l++) {
        float u = sus[l];
        u64p u2 = pk2(u, u);
        u64p acc2 = 0ull;
#pragma unroll
        for (int p = 0; p < 4; p++) {
            u64p nr = fma2(lr2[p], sr2[p], u2);
            nr = fma2(nli2[p], si2[p], nr);
            u64p ni = fma2(li2[p], sr2[p], mul2(lr2[p], si2[p]));
            sr2[p] = nr; si2[p] = ni;
            acc2 = fma2(ckr2[p], nr, acc2);
            acc2 = fma2(cki2[p], ni, acc2);
        }
        float a0, a1; upk2(acc2, a0, a1);
        float acc = a0 + a1;
        acc += __shfl_xor_sync(0xffffffffu, acc, 1);
        acc += __shfl_xor_sync(0xffffffffu, acc, 2);
        if (sub == 0) sys[l] = fmaf(Dh, u, acc);
    }
    __syncthreads();

    // phase 4: coalesced GELU + bf16split + store
#pragma unroll
    for (int it = 0; it < 16; it++) {
        int i = it * 256 + tid;
        int sg = i >> 6;
        int l = i & 63;
        float y = sy[sg * 65 + l];
        float gel = 0.5f * y * (1.f + erff(y * 0.70710678118654752f));
        g_gpk[base + i] = bf16split(gel);
    }
}

// ---------------------------------------------------------------------------
// GLU GEMM on tensor cores: mma.m16n8k16 bf16 hi/lo split, ldmatrix loads.
// ---------------------------------------------------------------------------
#define KC 32
#define SPAD 40   // u16 row stride (80B): conflict-free for LDSM 8-row pattern

__device__ __forceinline__ void mma16816(float* c, const unsigned* a, const unsigned* b) {
    asm volatile(
        "mma.sync.aligned.m16n8k16.row.col.f32.bf16.bf16.f32 "
        "{%0,%1,%2,%3}, {%4,%5,%6,%7}, {%8,%9}, {%0,%1,%2,%3};"
        : "+f"(c[0]), "+f"(c[1]), "+f"(c[2]), "+f"(c[3])
        : "r"(a[0]), "r"(a[1]), "r"(a[2]), "r"(a[3]), "r"(b[0]), "r"(b[1]));
}

__global__ void __launch_bounds__(256)
glu_mma_kernel(const float* __restrict__ glu_b, int layer) {
    __shared__ unsigned short sWhi[128 * SPAD];
    __shared__ unsigned short sWlo[128 * SPAD];
    __shared__ unsigned short sGhi[128 * SPAD];   // [col l][k]
    __shared__ unsigned short sGlo[128 * SPAD];

    const int tid = threadIdx.x;
    const int warp = tid >> 5, lane = tid & 31;
    const int gid = lane >> 2, tig = lane & 3;
    const int warp_m = warp & 1, warp_n = warp >> 1;
    const int j0 = blockIdx.y * 64;
    const int n0 = blockIdx.x * 128;
    const int b = n0 >> 12, l0 = n0 & (Lv - 1);

    const unsigned* wpk = g_wpk + (size_t)layer * 512 * 256;

    float acc[4][4][4];
#pragma unroll
    for (int t = 0; t < 4; t++)
#pragma unroll
        for (int n = 0; n < 4; n++)
#pragma unroll
            for (int c = 0; c < 4; c++) acc[t][n][c] = 0.f;

    // ldmatrix lane addressing offsets
    const int lrow = lane & 15;
    const int lcol8 = (lane >> 4) * 8;

    for (int kc = 0; kc < Hv; kc += KC) {
        __syncthreads();
#pragma unroll
        for (int i = tid; i < 128 * KC; i += 256) {
            int row = i >> 5;
            int k = i & (KC - 1);
            int grow = (row < 64) ? (j0 + row) : (256 + j0 + row - 64);
            unsigned v = wpk[grow * Hv + kc + k];
            sWhi[row * SPAD + k] = (unsigned short)(v & 0xffffu);
            sWlo[row * SPAD + k] = (unsigned short)(v >> 16);
        }
#pragma unroll
        for (int i = tid; i < KC * 128; i += 256) {
            int h = i >> 7;
            int l = i & 127;
            unsigned v = g_gpk[((size_t)(b * Hv + kc + h)) * Lv + l0 + l];
            sGhi[l * SPAD + h] = (unsigned short)(v & 0xffffu);
            sGlo[l * SPAD + h] = (unsigned short)(v >> 16);
        }
        __syncthreads();

#pragma unroll
        for (int ks = 0; ks < KC / 16; ks++) {
            const int kb = ks * 16;
            unsigned ahi[4][4], alo[4][4];
#pragma unroll
            for (int t4 = 0; t4 < 4; t4++) {
                int rowb = ((t4 >> 1) ? 64 : 0) + 32 * warp_m + 16 * (t4 & 1);
                ldsm4(ahi[t4][0], ahi[t4][1], ahi[t4][2], ahi[t4][3],
                      &sWhi[(rowb + lrow) * SPAD + kb + lcol8]);
                ldsm4(alo[t4][0], alo[t4][1], alo[t4][2], alo[t4][3],
                      &sWlo[(rowb + lrow) * SPAD + kb + lcol8]);
            }
            unsigned bhi[4][2], blo[4][2];
#pragma unroll
            for (int half = 0; half < 2; half++) {
                int nb = 32 * warp_n + 16 * half;
                unsigned q0, q1, q2, q3;
                ldsm4(q0, q1, q2, q3, &sGhi[(nb + lrow) * SPAD + kb + lcol8]);
                bhi[2 * half][0] = q0; bhi[2 * half][1] = q2;
                bhi[2 * half + 1][0] = q1; bhi[2 * half + 1][1] = q3;
                ldsm4(q0, q1, q2, q3, &sGlo[(nb + lrow) * SPAD + kb + lcol8]);
                blo[2 * half][0] = q0; blo[2 * half][1] = q2;
                blo[2 * half + 1][0] = q1; blo[2 * half + 1][1] = q3;
            }
#pragma unroll
            for (int t4 = 0; t4 < 4; t4++)
#pragma unroll
                for (int ni = 0; ni < 4; ni++) {
                    mma16816(acc[t4][ni], ahi[t4], bhi[ni]);
                    mma16816(acc[t4][ni], ahi[t4], blo[ni]);
                    mma16816(acc[t4][ni], alo[t4], bhi[ni]);
                }
        }
    }

    // epilogue: bias + GLU gate + store fp32
    const float* bbase = glu_b + (size_t)layer * 512;
#pragma unroll
    for (int mi = 0; mi < 2; mi++) {
        int r0 = j0 + 32 * warp_m + 16 * mi + gid;
        float ba0 = bbase[r0],       ba1 = bbase[r0 + 8];
        float bg0 = bbase[r0 + 256], bg1 = bbase[r0 + 264];
#pragma unroll
        for (int ni = 0; ni < 4; ni++) {
            int col = n0 + 32 * warp_n + 8 * ni + 2 * tig;
            int lcol = col & (Lv - 1);
            float a0 = acc[mi][ni][0] + ba0, a1 = acc[mi][ni][1] + ba0;
            float a2 = acc[mi][ni][2] + ba1, a3 = acc[mi][ni][3] + ba1;
            float q0 = acc[mi + 2][ni][0] + bg0, q1 = acc[mi + 2][ni][1] + bg0;
            float q2 = acc[mi + 2][ni][2] + bg1, q3 = acc[mi + 2][ni][3] + bg1;
            float z0 = a0 * (1.f / (1.f + expf(-q0)));
            float z1 = a1 * (1.f / (1.f + expf(-q1)));
            float z2 = a2 * (1.f / (1.f + expf(-q2)));
            float z3 = a3 * (1.f / (1.f + expf(-q3)));
            *(float2*)&g_z[((size_t)(b * Hv + r0)) * Lv + lcol]     = make_float2(z0, z1);
            *(float2*)&g_z[((size_t)(b * Hv + r0 + 8)) * Lv + lcol] = make_float2(z2, z3);
        }
    }
}

// ---------------------------------------------------------------------------
// Residual + LayerNorm, single-pass smem tile: block per 32 (b,l) columns.
// ---------------------------------------------------------------------------
__global__ void __launch_bounds__(256)
ln_kernel(const float* __restrict__ ln_g,
          const float* __restrict__ ln_b,
          int layer) {
    __shared__ float sv[256][33];
    __shared__ float red[2][8][32];
    __shared__ float smu[32], srs[32];

    const int tid = threadIdx.x;
    const int c = tid & 31, hg = tid >> 5;
    const int col0 = blockIdx.x * 32;
    const int b = col0 >> 12;
    const int l0 = col0 & (Lv - 1);

    float s = 0.f, s2 = 0.f;
#pragma unroll 8
    for (int i = 0; i < 32; i++) {
        int h = hg * 32 + i;
        size_t idx = ((size_t)(b * Hv + h)) * Lv + l0 + c;
        float v = g_z[idx] + g_h[idx];
        sv[h][c] = v;
        s += v;
        s2 = fmaf(v, v, s2);
    }
    red[0][hg][c] = s;
    red[1][hg][c] = s2;
    __syncthreads();
    if (hg == 0) {
        float ts = 0.f, ts2 = 0.f;
#pragma unroll
        for (int g = 0; g < 8; g++) { ts += red[0][g][c]; ts2 += red[1][g][c]; }
        float mu = ts * (1.f / Hv);
        smu[c] = mu;
        srs[c] = rsqrtf(ts2 * (1.f / Hv) - mu * mu + LN_EPS);
    }
    __syncthreads();
    const float mu = smu[c], rs = srs[c];
    const float* lg = ln_g + layer * Hv;
    const float* lb = ln_b + layer * Hv;
#pragma unroll 8
    for (int i = 0; i < 32; i++) {
        int h = hg * 32 + i;
        float v = (sv[h][c] - mu) * rs;
        g_h[((size_t)(b * Hv + h)) * Lv + l0 + c] = fmaf(v, lg[h], lb[h]);
    }
}

// ---------------------------------------------------------------------------
// Decoder
// ---------------------------------------------------------------------------
__global__ void __launch_bounds__(256)
dec_kernel(const float* __restrict__ dec1_w,
           const float* __restrict__ dec1_b,
           const float* __restrict__ dec2_w,
           const float* __restrict__ dec2_b,
           float* __restrict__ out) {
    int b = blockIdx.x;
    int j = threadIdx.x;
    const float* hr = g_h + ((size_t)(b * Hv + j)) * Lv;
    float acc = 0.f;
    for (int l = 0; l < Lv; l += 4) {
        float4 hv = *(const float4*)&hr[l];
        float4 wv = *(const float4*)&dec1_w[l];
        acc = fmaf(hv.x, wv.x, acc);
        acc = fmaf(hv.y, wv.y, acc);
        acc = fmaf(hv.z, wv.z, acc);
        acc = fmaf(hv.w, wv.w, acc);
    }
    acc += dec1_b[0];
    acc *= dec2_w[j];

    __shared__ float red[256];
    red[j] = acc;
    __syncthreads();
#pragma unroll
    for (int off = 128; off > 0; off >>= 1) {
        if (j < off) red[j] += red[j + off];
        __syncthreads();
    }
    if (j == 0) {
        float y = red[0] + dec2_b[0];
        out[b] = 1.f / (1.f + expf(-y));
    }
}

// ---------------------------------------------------------------------------
extern "C" void kernel_launch(void* const* d_in, const int* in_sizes, int n_in,
                              void* d_out, int out_size) {
    const float* x          = (const float*)d_in[0];
    const float* enc_w      = (const float*)d_in[1];
    const float* enc_b      = (const float*)d_in[2];
    const float* log_dt     = (const float*)d_in[3];
    const float* log_A_real = (const float*)d_in[4];
    const float* A_imag     = (const float*)d_in[5];
    const float* C_re       = (const float*)d_in[6];
    const float* C_im       = (const float*)d_in[7];
    const float* Dp         = (const float*)d_in[8];
    const float* glu_w      = (const float*)d_in[9];
    const float* glu_b      = (const float*)d_in[10];
    const float* ln_g       = (const float*)d_in[11];
    const float* ln_b       = (const float*)d_in[12];
    const float* dec1_w     = (const float*)d_in[13];
    const float* dec1_b     = (const float*)d_in[14];
    const float* dec2_w     = (const float*)d_in[15];
    const float* dec2_b     = (const float*)d_in[16];
    float* out = (float*)d_out;

    enc_kernel<<<32768, 256>>>(x, enc_w, enc_b);
    wconv_kernel<<<NLv * 512, 256>>>(glu_w);

    for (int layer = 0; layer < NLv; layer++) {
        scan_gelu_kernel<<<Bv * Hv, 256>>>(
            log_dt, log_A_real, A_imag, C_re, C_im, Dp, layer);
        glu_mma_kernel<<<dim3((Bv * Lv) / 128, Hv / 64), 256>>>(glu_b, layer);
        ln_kernel<<<(Bv * Lv) / 32, 256>>>(ln_g, ln_b, layer);
    }

    dec_kernel<<<Bv, 256>>>(dec1_w, dec1_b, dec2_w, dec2_b, out);
}

// round 11
// speedup vs baseline: 1.9237x; 1.0896x over previous
#include <cuda_runtime.h>
#include <cuda_bf16.h>
#include <math.h>

// Problem constants
#define Bv 32
#define Lv 4096
#define Hv 256
#define NLv 4
#define N2v 32
#define LN_EPS 1e-5f

// Scratch (allocation-free rule: device globals)
__device__ float    g_h[(size_t)Bv * Hv * Lv];    // activations (B,H,L) fp32
__device__ unsigned g_gpk[(size_t)Bv * Hv * Lv];  // gelu output, packed bf16 hi|lo<<16
__device__ float    g_z[(size_t)Bv * Hv * Lv];    // GLU output fp32
__device__ unsigned g_wpk[NLv * 512 * 256];       // packed W hi/lo, all layers

// ---------------------------------------------------------------------------
// f32x2 helpers
// ---------------------------------------------------------------------------
typedef unsigned long long u64p;
__device__ __forceinline__ u64p pk2(float lo, float hi) {
    u64p r; asm("mov.b64 %0, {%1,%2};" : "=l"(r) : "f"(lo), "f"(hi)); return r;
}
__device__ __forceinline__ void upk2(u64p v, float& lo, float& hi) {
    asm("mov.b64 {%0,%1}, %2;" : "=f"(lo), "=f"(hi) : "l"(v));
}
__device__ __forceinline__ u64p fma2(u64p a, u64p b, u64p c) {
    u64p d; asm("fma.rn.f32x2 %0, %1, %2, %3;" : "=l"(d) : "l"(a), "l"(b), "l"(c)); return d;
}
__device__ __forceinline__ u64p mul2(u64p a, u64p b) {
    u64p d; asm("mul.rn.f32x2 %0, %1, %2;" : "=l"(d) : "l"(a), "l"(b)); return d;
}

// bf16 split pack: hi = bf16(x), lo = bf16(x - hi), packed hi | lo<<16
__device__ __forceinline__ unsigned bf16split(float x) {
    __nv_bfloat16 h = __float2bfloat16(x);
    float hf = __bfloat162float(h);
    __nv_bfloat16 l = __float2bfloat16(x - hf);
    return (unsigned)__bfloat16_as_ushort(h) | ((unsigned)__bfloat16_as_ushort(l) << 16);
}

__device__ __forceinline__ void ldsm4(unsigned& r0, unsigned& r1, unsigned& r2, unsigned& r3,
                                      const void* p) {
    unsigned a = (unsigned)__cvta_generic_to_shared(p);
    asm volatile("ldmatrix.sync.aligned.m8n8.x4.shared.b16 {%0,%1,%2,%3}, [%4];"
                 : "=r"(r0), "=r"(r1), "=r"(r2), "=r"(r3) : "r"(a));
}

// ---------------------------------------------------------------------------
// Encoder
// ---------------------------------------------------------------------------
__global__ void enc_kernel(const float* __restrict__ x,
                           const float* __restrict__ enc_w,
                           const float* __restrict__ enc_b) {
    size_t t = (size_t)blockIdx.x * blockDim.x + threadIdx.x;
    size_t idx4 = t * 4;
    int l = (int)(idx4 & (Lv - 1));
    int j = (int)((idx4 >> 12) & (Hv - 1));
    int b = (int)(idx4 >> 20);
    float w = enc_w[j];
    float bias = enc_b[j];
    const float4 xv = *(const float4*)&x[(size_t)b * Lv + l];
    float4 o;
    o.x = fmaf(xv.x, w, bias);
    o.y = fmaf(xv.y, w, bias);
    o.z = fmaf(xv.z, w, bias);
    o.w = fmaf(xv.w, w, bias);
    *(float4*)&g_h[idx4] = o;
}

// ---------------------------------------------------------------------------
// W conversion: pack all layers' glu_w into bf16 hi/lo u32 (one launch)
// ---------------------------------------------------------------------------
__global__ void wconv_kernel(const float* __restrict__ glu_w) {
    int i = blockIdx.x * 256 + threadIdx.x;
    g_wpk[i] = bf16split(glu_w[i]);
}

// ---------------------------------------------------------------------------
// Segment-parallel S4D scan + D skip + GELU + bf16 pack.
// In-place y (no separate sy buffer) -> smem ~34KB -> more resident CTAs.
// ---------------------------------------------------------------------------
#define NSEG 64
#define SGT 64

__global__ void __launch_bounds__(256)
scan_gelu_kernel(const float* __restrict__ log_dt,
                 const float* __restrict__ log_A_real,
                 const float* __restrict__ A_imag,
                 const float* __restrict__ C_re,
                 const float* __restrict__ C_im,
                 const float* __restrict__ Dp,
                 int layer) {
    __shared__ float su[NSEG * 65];
    __shared__ float2 sE[NSEG][33];
    __shared__ float4 sCoef[32];   // (lr, li, ckr, cki) per state

    const int tid = threadIdx.x;
    const int sub = tid & 3;
    const int seg = tid >> 2;
    const int seq = blockIdx.x;          // 0..8191
    const int hh = seq & (Hv - 1);
    const size_t base = (size_t)seq * Lv;

    // stage u into smem (padded [seg][65] layout), coalesced float4 reads
#pragma unroll
    for (int it = 0; it < 4; it++) {
        int i = it * 256 + tid;              // 0..1023 float4s
        float4 v = *(const float4*)&g_h[base + (size_t)i * 4];
        int sg = i >> 4;
        int l = (i & 15) * 4;
        float* p = &su[sg * 65 + l];
        p[0] = v.x; p[1] = v.y; p[2] = v.z; p[3] = v.w;
    }

    // per-state coefficients (32 threads, shared)
    if (tid < 32) {
        int n = tid;
        const int pb = (layer * Hv + hh) * N2v + n;
        float dt = expf(log_dt[layer * Hv + hh]);
        float Ar = -expf(log_A_real[pb]);
        float Ai = A_imag[pb];
        float dAr = Ar * dt, dAi = Ai * dt;
        float e = expf(dAr);
        float lrr = e * cosf(dAi);
        float lii = e * sinf(dAi);
        float cr = C_re[pb], ci = C_im[pb];
        float nr = cr * (lrr - 1.f) - ci * lii;
        float ni = cr * lii + ci * (lrr - 1.f);
        float inv = 1.f / (Ar * Ar + Ai * Ai);
        float ckr =  2.f * (nr * Ar + ni * Ai) * inv;
        float cki = -2.f * (ni * Ar - nr * Ai) * inv;
        sCoef[n] = make_float4(lrr, lii, ckr, cki);
    }
    __syncthreads();

    // load per-thread packed coefficients (8 states = 4 pairs)
    u64p lr2[4], li2[4], nli2[4], ckr2[4], cki2[4], sr2[4], si2[4];
#pragma unroll
    for (int p = 0; p < 4; p++) {
        float4 c0 = sCoef[sub * 8 + 2 * p];
        float4 c1 = sCoef[sub * 8 + 2 * p + 1];
        lr2[p]  = pk2(c0.x, c1.x);
        li2[p]  = pk2(c0.y, c1.y);
        nli2[p] = pk2(-c0.y, -c1.y);
        ckr2[p] = pk2(c0.z, c1.z);
        cki2[p] = pk2(c0.w, c1.w);
        sr2[p] = 0ull; si2[p] = 0ull;
    }
    const float Dh = Dp[layer * Hv + hh];
    float* sus = &su[seg * 65];

    // phase 1: zero-init segment scan (state update only)
#pragma unroll 4
    for (int l = 0; l < SGT; l++) {
        float u = sus[l];
        u64p u2 = pk2(u, u);
#pragma unroll
        for (int p = 0; p < 4; p++) {
            u64p nr = fma2(lr2[p], sr2[p], u2);
            nr = fma2(nli2[p], si2[p], nr);
            u64p ni = fma2(li2[p], sr2[p], mul2(lr2[p], si2[p]));
            sr2[p] = nr; si2[p] = ni;
        }
    }
#pragma unroll
    for (int p = 0; p < 4; p++) {
        float r0, r1, i0, i1;
        upk2(sr2[p], r0, r1);
        upk2(si2[p], i0, i1);
        sE[seg][sub * 8 + 2 * p]     = make_float2(r0, i0);
        sE[seg][sub * 8 + 2 * p + 1] = make_float2(r1, i1);
    }
    __syncthreads();

    // phase 2: compose boundary states (one thread per state)
    if (tid < 32) {
        float4 c = sCoef[tid];
        float tr = c.x, ti = c.y;   // lambda
#pragma unroll
        for (int q = 0; q < 6; q++) {   // lambda^64 by squaring
            float nr = tr * tr - ti * ti;
            float ni = 2.f * tr * ti;
            tr = nr; ti = ni;
        }
        float sr = 0.f, si = 0.f;
        for (int cseg = 0; cseg < NSEG; cseg++) {
            float2 e = sE[cseg][tid];
            sE[cseg][tid] = make_float2(sr, si);   // s_in for this segment
            float nr = tr * sr - ti * si + e.x;
            float ni = tr * si + ti * sr + e.y;
            sr = nr; si = ni;
        }
    }
    __syncthreads();

    // phase 3: rescan with correct initial state, write y in-place into su
#pragma unroll
    for (int p = 0; p < 4; p++) {
        float2 a = sE[seg][sub * 8 + 2 * p];
        float2 b2 = sE[seg][sub * 8 + 2 * p + 1];
        sr2[p] = pk2(a.x, b2.x);
        si2[p] = pk2(a.y, b2.y);
    }
#pragma unroll 4
    for (int l = 0; l < SGT; l++) {
        float u = sus[l];
        u64p u2 = pk2(u, u);
        u64p acc2 = 0ull;
#pragma unroll
        for (int p = 0; p < 4; p++) {
            u64p nr = fma2(lr2[p], sr2[p], u2);
            nr = fma2(nli2[p], si2[p], nr);
            u64p ni = fma2(li2[p], sr2[p], mul2(lr2[p], si2[p]));
            sr2[p] = nr; si2[p] = ni;
            acc2 = fma2(ckr2[p], nr, acc2);
            acc2 = fma2(cki2[p], ni, acc2);
        }
        float a0, a1; upk2(acc2, a0, a1);
        float acc = a0 + a1;
        acc += __shfl_xor_sync(0xffffffffu, acc, 1);
        acc += __shfl_xor_sync(0xffffffffu, acc, 2);
        if (sub == 0) sus[l] = fmaf(Dh, u, acc);   // in-place (warp-lockstep safe)
    }
    __syncthreads();

    // phase 4: coalesced GELU + bf16split + store
#pragma unroll
    for (int it = 0; it < 16; it++) {
        int i = it * 256 + tid;
        int sg = i >> 6;
        int l = i & 63;
        float y = su[sg * 65 + l];
        float gel = 0.5f * y * (1.f + erff(y * 0.70710678118654752f));
        g_gpk[base + i] = bf16split(gel);
    }
}

// ---------------------------------------------------------------------------
// GLU GEMM, mma.m16n8k16 bf16 hi/lo split, ldmatrix.
// Tile: 64 a-rows + 64 g-rows x 64 cols. 8 warps = 2 warp_m x 4 warp_n.
// Small tile -> ~100 regs -> 2 CTAs/SM (latency hiding).
// ---------------------------------------------------------------------------
#define KC 32
#define SPAD 40   // u16 row stride (80B)

__device__ __forceinline__ void mma16816(float* c, const unsigned* a, const unsigned* b) {
    asm volatile(
        "mma.sync.aligned.m16n8k16.row.col.f32.bf16.bf16.f32 "
        "{%0,%1,%2,%3}, {%4,%5,%6,%7}, {%8,%9}, {%0,%1,%2,%3};"
        : "+f"(c[0]), "+f"(c[1]), "+f"(c[2]), "+f"(c[3])
        : "r"(a[0]), "r"(a[1]), "r"(a[2]), "r"(a[3]), "r"(b[0]), "r"(b[1]));
}

__global__ void __launch_bounds__(256, 2)
glu_mma_kernel(const float* __restrict__ glu_b, int layer) {
    __shared__ unsigned short sWhi[128 * SPAD];
    __shared__ unsigned short sWlo[128 * SPAD];
    __shared__ unsigned short sGhi[64 * SPAD];    // [col l][k]
    __shared__ unsigned short sGlo[64 * SPAD];

    const int tid = threadIdx.x;
    const int warp = tid >> 5, lane = tid & 31;
    const int gid = lane >> 2, tig = lane & 3;
    const int warp_m = warp & 1, warp_n = warp >> 1;
    const int j0 = blockIdx.y * 64;
    const int n0 = blockIdx.x * 64;
    const int b = n0 >> 12, l0 = n0 & (Lv - 1);

    const unsigned* wpk = g_wpk + (size_t)layer * 512 * 256;

    float acc[4][2][4];   // [a-m0, a-m1, g-m0, g-m1][ni][c]
#pragma unroll
    for (int t = 0; t < 4; t++)
#pragma unroll
        for (int n = 0; n < 2; n++)
#pragma unroll
            for (int c = 0; c < 4; c++) acc[t][n][c] = 0.f;

    const int lrow = lane & 15;
    const int lcol8 = (lane >> 4) * 8;

    for (int kc = 0; kc < Hv; kc += KC) {
        __syncthreads();
        // W tile: 128 rows (64 a + 64 g) x KC
#pragma unroll
        for (int it = 0; it < 16; it++) {
            int i = tid + it * 256;
            int row = i >> 5;
            int k = i & (KC - 1);
            int grow = (row < 64) ? (j0 + row) : (256 + j0 + row - 64);
            unsigned v = wpk[grow * Hv + kc + k];
            sWhi[row * SPAD + k] = (unsigned short)(v & 0xffffu);
            sWlo[row * SPAD + k] = (unsigned short)(v >> 16);
        }
        // G tile: 64 cols x KC, transposed into [l][k]
#pragma unroll
        for (int it = 0; it < 8; it++) {
            int i = tid + it * 256;
            int l = i & 63;
            int h = i >> 6;
            unsigned v = g_gpk[((size_t)(b * Hv + kc + h)) * Lv + l0 + l];
            sGhi[l * SPAD + h] = (unsigned short)(v & 0xffffu);
            sGlo[l * SPAD + h] = (unsigned short)(v >> 16);
        }
        __syncthreads();

#pragma unroll
        for (int ks = 0; ks < KC / 16; ks++) {
            const int kb = ks * 16;
            unsigned ahi[4][4], alo[4][4];
#pragma unroll
            for (int t4 = 0; t4 < 4; t4++) {
                int rowb = ((t4 >> 1) ? 64 : 0) + 32 * warp_m + 16 * (t4 & 1);
                ldsm4(ahi[t4][0], ahi[t4][1], ahi[t4][2], ahi[t4][3],
                      &sWhi[(rowb + lrow) * SPAD + kb + lcol8]);
                ldsm4(alo[t4][0], alo[t4][1], alo[t4][2], alo[t4][3],
                      &sWlo[(rowb + lrow) * SPAD + kb + lcol8]);
            }
            unsigned bhi[2][2], blo[2][2];
            {
                int nb = 16 * warp_n;
                unsigned q0, q1, q2, q3;
                ldsm4(q0, q1, q2, q3, &sGhi[(nb + lrow) * SPAD + kb + lcol8]);
                bhi[0][0] = q0; bhi[0][1] = q2;
                bhi[1][0] = q1; bhi[1][1] = q3;
                ldsm4(q0, q1, q2, q3, &sGlo[(nb + lrow) * SPAD + kb + lcol8]);
                blo[0][0] = q0; blo[0][1] = q2;
                blo[1][0] = q1; blo[1][1] = q3;
            }
#pragma unroll
            for (int t4 = 0; t4 < 4; t4++)
#pragma unroll
                for (int ni = 0; ni < 2; ni++) {
                    mma16816(acc[t4][ni], ahi[t4], bhi[ni]);
                    mma16816(acc[t4][ni], ahi[t4], blo[ni]);
                    mma16816(acc[t4][ni], alo[t4], bhi[ni]);
                }
        }
    }

    // epilogue: bias + GLU gate + store fp32
    const float* bbase = glu_b + (size_t)layer * 512;
#pragma unroll
    for (int mi = 0; mi < 2; mi++) {
        int r0 = j0 + 32 * warp_m + 16 * mi + gid;
        float ba0 = bbase[r0],       ba1 = bbase[r0 + 8];
        float bg0 = bbase[r0 + 256], bg1 = bbase[r0 + 264];
#pragma unroll
        for (int ni = 0; ni < 2; ni++) {
            int lcol = l0 + 16 * warp_n + 8 * ni + 2 * tig;
            float a0 = acc[mi][ni][0] + ba0, a1 = acc[mi][ni][1] + ba0;
            float a2 = acc[mi][ni][2] + ba1, a3 = acc[mi][ni][3] + ba1;
            float q0 = acc[mi + 2][ni][0] + bg0, q1 = acc[mi + 2][ni][1] + bg0;
            float q2 = acc[mi + 2][ni][2] + bg1, q3 = acc[mi + 2][ni][3] + bg1;
            float z0 = a0 * (1.f / (1.f + expf(-q0)));
            float z1 = a1 * (1.f / (1.f + expf(-q1)));
            float z2 = a2 * (1.f / (1.f + expf(-q2)));
            float z3 = a3 * (1.f / (1.f + expf(-q3)));
            *(float2*)&g_z[((size_t)(b * Hv + r0)) * Lv + lcol]     = make_float2(z0, z1);
            *(float2*)&g_z[((size_t)(b * Hv + r0 + 8)) * Lv + lcol] = make_float2(z2, z3);
        }
    }
}

// ---------------------------------------------------------------------------
// Residual + LayerNorm, single-pass smem tile: block per 32 (b,l) columns.
// ---------------------------------------------------------------------------
__global__ void __launch_bounds__(256)
ln_kernel(const float* __restrict__ ln_g,
          const float* __restrict__ ln_b,
          int layer) {
    __shared__ float sv[256][33];
    __shared__ float red[2][8][32];
    __shared__ float smu[32], srs[32];

    const int tid = threadIdx.x;
    const int c = tid & 31, hg = tid >> 5;
    const int col0 = blockIdx.x * 32;
    const int b = col0 >> 12;
    const int l0 = col0 & (Lv - 1);

    float s = 0.f, s2 = 0.f;
#pragma unroll 8
    for (int i = 0; i < 32; i++) {
        int h = hg * 32 + i;
        size_t idx = ((size_t)(b * Hv + h)) * Lv + l0 + c;
        float v = g_z[idx] + g_h[idx];
        sv[h][c] = v;
        s += v;
        s2 = fmaf(v, v, s2);
    }
    red[0][hg][c] = s;
    red[1][hg][c] = s2;
    __syncthreads();
    if (hg == 0) {
        float ts = 0.f, ts2 = 0.f;
#pragma unroll
        for (int g = 0; g < 8; g++) { ts += red[0][g][c]; ts2 += red[1][g][c]; }
        float mu = ts * (1.f / Hv);
        smu[c] = mu;
        srs[c] = rsqrtf(ts2 * (1.f / Hv) - mu * mu + LN_EPS);
    }
    __syncthreads();
    const float mu = smu[c], rs = srs[c];
    const float* lg = ln_g + layer * Hv;
    const float* lb = ln_b + layer * Hv;
#pragma unroll 8
    for (int i = 0; i < 32; i++) {
        int h = hg * 32 + i;
        float v = (sv[h][c] - mu) * rs;
        g_h[((size_t)(b * Hv + h)) * Lv + l0 + c] = fmaf(v, lg[h], lb[h]);
    }
}

// ---------------------------------------------------------------------------
// Decoder
// ---------------------------------------------------------------------------
__global__ void __launch_bounds__(256)
dec_kernel(const float* __restrict__ dec1_w,
           const float* __restrict__ dec1_b,
           const float* __restrict__ dec2_w,
           const float* __restrict__ dec2_b,
           float* __restrict__ out) {
    int b = blockIdx.x;
    int j = threadIdx.x;
    const float* hr = g_h + ((size_t)(b * Hv + j)) * Lv;
    float acc = 0.f;
    for (int l = 0; l < Lv; l += 4) {
        float4 hv = *(const float4*)&hr[l];
        float4 wv = *(const float4*)&dec1_w[l];
        acc = fmaf(hv.x, wv.x, acc);
        acc = fmaf(hv.y, wv.y, acc);
        acc = fmaf(hv.z, wv.z, acc);
        acc = fmaf(hv.w, wv.w, acc);
    }
    acc += dec1_b[0];
    acc *= dec2_w[j];

    __shared__ float red[256];
    red[j] = acc;
    __syncthreads();
#pragma unroll
    for (int off = 128; off > 0; off >>= 1) {
        if (j < off) red[j] += red[j + off];
        __syncthreads();
    }
    if (j == 0) {
        float y = red[0] + dec2_b[0];
        out[b] = 1.f / (1.f + expf(-y));
    }
}

// ---------------------------------------------------------------------------
extern "C" void kernel_launch(void* const* d_in, const int* in_sizes, int n_in,
                              void* d_out, int out_size) {
    const float* x          = (const float*)d_in[0];
    const float* enc_w      = (const float*)d_in[1];
    const float* enc_b      = (const float*)d_in[2];
    const float* log_dt     = (const float*)d_in[3];
    const float* log_A_real = (const float*)d_in[4];
    const float* A_imag     = (const float*)d_in[5];
    const float* C_re       = (const float*)d_in[6];
    const float* C_im       = (const float*)d_in[7];
    const float* Dp         = (const float*)d_in[8];
    const float* glu_w      = (const float*)d_in[9];
    const float* glu_b      = (const float*)d_in[10];
    const float* ln_g       = (const float*)d_in[11];
    const float* ln_b       = (const float*)d_in[12];
    const float* dec1_w     = (const float*)d_in[13];
    const float* dec1_b     = (const float*)d_in[14];
    const float* dec2_w     = (const float*)d_in[15];
    const float* dec2_b     = (const float*)d_in[16];
    float* out = (float*)d_out;

    enc_kernel<<<32768, 256>>>(x, enc_w, enc_b);
    wconv_kernel<<<NLv * 512, 256>>>(glu_w);

    for (int layer = 0; layer < NLv; layer++) {
        scan_gelu_kernel<<<Bv * Hv, 256>>>(
            log_dt, log_A_real, A_imag, C_re, C_im, Dp, layer);
        glu_mma_kernel<<<dim3((Bv * Lv) / 64, Hv / 64), 256>>>(glu_b, layer);
        ln_kernel<<<(Bv * Lv) / 32, 256>>>(ln_g, ln_b, layer);
    }

    dec_kernel<<<Bv, 256>>>(dec1_w, dec1_b, dec2_w, dec2_b, out);
}

// round 13
// speedup vs baseline: 2.1248x; 1.1045x over previous
#include <cuda_runtime.h>
#include <cuda_bf16.h>
#include <math.h>

// Problem constants
#define Bv 32
#define Lv 4096
#define Hv 256
#define NLv 4
#define N2v 32
#define LN_EPS 1e-5f

// Scratch (allocation-free rule: device globals)
__device__ float g_h[(size_t)Bv * Hv * Lv];   // activations (B,H,L) fp32
__device__ float g_z[(size_t)Bv * Hv * Lv];   // GLU output fp32
__device__ unsigned short g_ghi[(size_t)Bv * Hv * Lv];  // gelu bf16 hi plane
__device__ unsigned short g_glo[(size_t)Bv * Hv * Lv];  // gelu bf16 lo plane
__device__ unsigned short g_whi[NLv * 512 * 256];       // W bf16 hi plane
__device__ unsigned short g_wlo[NLv * 512 * 256];       // W bf16 lo plane

// ---------------------------------------------------------------------------
// f32x2 helpers
// ---------------------------------------------------------------------------
typedef unsigned long long u64p;
__device__ __forceinline__ u64p pk2(float lo, float hi) {
    u64p r; asm("mov.b64 %0, {%1,%2};" : "=l"(r) : "f"(lo), "f"(hi)); return r;
}
__device__ __forceinline__ void upk2(u64p v, float& lo, float& hi) {
    asm("mov.b64 {%0,%1}, %2;" : "=f"(lo), "=f"(hi) : "l"(v));
}
__device__ __forceinline__ u64p fma2(u64p a, u64p b, u64p c) {
    u64p d; asm("fma.rn.f32x2 %0, %1, %2, %3;" : "=l"(d) : "l"(a), "l"(b), "l"(c)); return d;
}
__device__ __forceinline__ u64p mul2(u64p a, u64p b) {
    u64p d; asm("mul.rn.f32x2 %0, %1, %2;" : "=l"(d) : "l"(a), "l"(b)); return d;
}

// bf16 split: hi = bf16(x), lo = bf16(x - hi)
__device__ __forceinline__ void bf16split2(float x, unsigned short& h, unsigned short& l) {
    __nv_bfloat16 hb = __float2bfloat16(x);
    float hf = __bfloat162float(hb);
    __nv_bfloat16 lb = __float2bfloat16(x - hf);
    h = __bfloat16_as_ushort(hb);
    l = __bfloat16_as_ushort(lb);
}

__device__ __forceinline__ void ldsm4(unsigned& r0, unsigned& r1, unsigned& r2, unsigned& r3,
                                      const void* p) {
    unsigned a = (unsigned)__cvta_generic_to_shared(p);
    asm volatile("ldmatrix.sync.aligned.m8n8.x4.shared.b16 {%0,%1,%2,%3}, [%4];"
                 : "=r"(r0), "=r"(r1), "=r"(r2), "=r"(r3) : "r"(a));
}
__device__ __forceinline__ void ldsm4t(unsigned& r0, unsigned& r1, unsigned& r2, unsigned& r3,
                                       const void* p) {
    unsigned a = (unsigned)__cvta_generic_to_shared(p);
    asm volatile("ldmatrix.sync.aligned.m8n8.x4.trans.shared.b16 {%0,%1,%2,%3}, [%4];"
                 : "=r"(r0), "=r"(r1), "=r"(r2), "=r"(r3) : "r"(a));
}

// ---------------------------------------------------------------------------
// Encoder
// ---------------------------------------------------------------------------
__global__ void enc_kernel(const float* __restrict__ x,
                           const float* __restrict__ enc_w,
                           const float* __restrict__ enc_b) {
    size_t t = (size_t)blockIdx.x * blockDim.x + threadIdx.x;
    size_t idx4 = t * 4;
    int l = (int)(idx4 & (Lv - 1));
    int j = (int)((idx4 >> 12) & (Hv - 1));
    int b = (int)(idx4 >> 20);
    float w = enc_w[j];
    float bias = enc_b[j];
    const float4 xv = *(const float4*)&x[(size_t)b * Lv + l];
    float4 o;
    o.x = fmaf(xv.x, w, bias);
    o.y = fmaf(xv.y, w, bias);
    o.z = fmaf(xv.z, w, bias);
    o.w = fmaf(xv.w, w, bias);
    *(float4*)&g_h[idx4] = o;
}

// ---------------------------------------------------------------------------
// W conversion: split all layers' glu_w into bf16 hi/lo planes
// ---------------------------------------------------------------------------
__global__ void wconv_kernel(const float* __restrict__ glu_w) {
    int i = blockIdx.x * 256 + threadIdx.x;
    unsigned short h, l;
    bf16split2(glu_w[i], h, l);
    g_whi[i] = h;
    g_wlo[i] = l;
}

// ---------------------------------------------------------------------------
// Segment-parallel S4D scan + D skip + GELU + bf16 hi/lo plane store.
// ---------------------------------------------------------------------------
#define NSEG 64
#define SGT 64

__global__ void __launch_bounds__(256)
scan_gelu_kernel(const float* __restrict__ log_dt,
                 const float* __restrict__ log_A_real,
                 const float* __restrict__ A_imag,
                 const float* __restrict__ C_re,
                 const float* __restrict__ C_im,
                 const float* __restrict__ Dp,
                 int layer) {
    __shared__ float su[NSEG * 65];
    __shared__ float2 sE[NSEG][33];
    __shared__ float4 sCoef[32];   // (lr, li, ckr, cki) per state

    const int tid = threadIdx.x;
    const int sub = tid & 3;
    const int seg = tid >> 2;
    const int seq = blockIdx.x;          // 0..8191
    const int hh = seq & (Hv - 1);
    const size_t base = (size_t)seq * Lv;

    // stage u into smem (padded [seg][65] layout)
#pragma unroll
    for (int it = 0; it < 4; it++) {
        int i = it * 256 + tid;
        float4 v = *(const float4*)&g_h[base + (size_t)i * 4];
        int sg = i >> 4;
        int l = (i & 15) * 4;
        float* p = &su[sg * 65 + l];
        p[0] = v.x; p[1] = v.y; p[2] = v.z; p[3] = v.w;
    }

    // per-state coefficients (32 threads, shared)
    if (tid < 32) {
        int n = tid;
        const int pb = (layer * Hv + hh) * N2v + n;
        float dt = expf(log_dt[layer * Hv + hh]);
        float Ar = -expf(log_A_real[pb]);
        float Ai = A_imag[pb];
        float dAr = Ar * dt, dAi = Ai * dt;
        float e = expf(dAr);
        float lrr = e * cosf(dAi);
        float lii = e * sinf(dAi);
        float cr = C_re[pb], ci = C_im[pb];
        float nr = cr * (lrr - 1.f) - ci * lii;
        float ni = cr * lii + ci * (lrr - 1.f);
        float inv = 1.f / (Ar * Ar + Ai * Ai);
        float ckr =  2.f * (nr * Ar + ni * Ai) * inv;
        float cki = -2.f * (ni * Ar - nr * Ai) * inv;
        sCoef[n] = make_float4(lrr, lii, ckr, cki);
    }
    __syncthreads();

    u64p lr2[4], li2[4], nli2[4], ckr2[4], cki2[4], sr2[4], si2[4];
#pragma unroll
    for (int p = 0; p < 4; p++) {
        float4 c0 = sCoef[sub * 8 + 2 * p];
        float4 c1 = sCoef[sub * 8 + 2 * p + 1];
        lr2[p]  = pk2(c0.x, c1.x);
        li2[p]  = pk2(c0.y, c1.y);
        nli2[p] = pk2(-c0.y, -c1.y);
        ckr2[p] = pk2(c0.z, c1.z);
        cki2[p] = pk2(c0.w, c1.w);
        sr2[p] = 0ull; si2[p] = 0ull;
    }
    const float Dh = Dp[layer * Hv + hh];
    float* sus = &su[seg * 65];

    // phase 1: zero-init segment scan (state update only)
#pragma unroll 4
    for (int l = 0; l < SGT; l++) {
        float u = sus[l];
        u64p u2 = pk2(u, u);
#pragma unroll
        for (int p = 0; p < 4; p++) {
            u64p nr = fma2(lr2[p], sr2[p], u2);
            nr = fma2(nli2[p], si2[p], nr);
            u64p ni = fma2(li2[p], sr2[p], mul2(lr2[p], si2[p]));
            sr2[p] = nr; si2[p] = ni;
        }
    }
#pragma unroll
    for (int p = 0; p < 4; p++) {
        float r0, r1, i0, i1;
        upk2(sr2[p], r0, r1);
        upk2(si2[p], i0, i1);
        sE[seg][sub * 8 + 2 * p]     = make_float2(r0, i0);
        sE[seg][sub * 8 + 2 * p + 1] = make_float2(r1, i1);
    }
    __syncthreads();

    // phase 2: compose boundary states (one thread per state)
    if (tid < 32) {
        float4 c = sCoef[tid];
        float tr = c.x, ti = c.y;
#pragma unroll
        for (int q = 0; q < 6; q++) {
            float nr = tr * tr - ti * ti;
            float ni = 2.f * tr * ti;
            tr = nr; ti = ni;
        }
        float sr = 0.f, si = 0.f;
        for (int cseg = 0; cseg < NSEG; cseg++) {
            float2 e = sE[cseg][tid];
            sE[cseg][tid] = make_float2(sr, si);
            float nr = tr * sr - ti * si + e.x;
            float ni = tr * si + ti * sr + e.y;
            sr = nr; si = ni;
        }
    }
    __syncthreads();

    // phase 3: rescan with correct initial state, y in-place
#pragma unroll
    for (int p = 0; p < 4; p++) {
        float2 a = sE[seg][sub * 8 + 2 * p];
        float2 b2 = sE[seg][sub * 8 + 2 * p + 1];
        sr2[p] = pk2(a.x, b2.x);
        si2[p] = pk2(a.y, b2.y);
    }
#pragma unroll 4
    for (int l = 0; l < SGT; l++) {
        float u = sus[l];
        u64p u2 = pk2(u, u);
        u64p acc2 = 0ull;
#pragma unroll
        for (int p = 0; p < 4; p++) {
            u64p nr = fma2(lr2[p], sr2[p], u2);
            nr = fma2(nli2[p], si2[p], nr);
            u64p ni = fma2(li2[p], sr2[p], mul2(lr2[p], si2[p]));
            sr2[p] = nr; si2[p] = ni;
            acc2 = fma2(ckr2[p], nr, acc2);
            acc2 = fma2(cki2[p], ni, acc2);
        }
        float a0, a1; upk2(acc2, a0, a1);
        float acc = a0 + a1;
        acc += __shfl_xor_sync(0xffffffffu, acc, 1);
        acc += __shfl_xor_sync(0xffffffffu, acc, 2);
        if (sub == 0) sus[l] = fmaf(Dh, u, acc);
    }
    __syncthreads();

    // phase 4: GELU + split + plane stores (2 l's per thread, u32 writes)
#pragma unroll
    for (int it = 0; it < 8; it++) {
        int i2 = it * 256 + tid;          // pair index
        int li = i2 * 2;
        int sg = li >> 6;
        int l = li & 63;
        float y0 = su[sg * 65 + l];
        float y1 = su[sg * 65 + l + 1];
        float ge0 = 0.5f * y0 * (1.f + erff(y0 * 0.70710678118654752f));
        float ge1 = 0.5f * y1 * (1.f + erff(y1 * 0.70710678118654752f));
        unsigned short h0, l0b, h1, l1b;
        bf16split2(ge0, h0, l0b);
        bf16split2(ge1, h1, l1b);
        *(unsigned*)&g_ghi[base + li] = (unsigned)h0 | ((unsigned)h1 << 16);
        *(unsigned*)&g_glo[base + li] = (unsigned)l0b | ((unsigned)l1b << 16);
    }
}

// ---------------------------------------------------------------------------
// GLU GEMM, mma.m16n8k16 bf16 hi/lo split.
// W in smem [j][k] (ldmatrix), G in smem [k][l] (ldmatrix.trans).
// All staging is uint4 copies from pre-split global planes.
// Tile: (64 a-rows + 64 g-rows) x 64 cols; 8 warps = 4 warp_m x 2 warp_n.
// ---------------------------------------------------------------------------
#define KC 32
#define SPAD 40   // W row stride in u16 (80B, odd multiple of 16B)
#define GPAD 72   // G row stride in u16 (144B, odd multiple of 16B)

__device__ __forceinline__ void mma16816(float* c, const unsigned* a, const unsigned* b) {
    asm volatile(
        "mma.sync.aligned.m16n8k16.row.col.f32.bf16.bf16.f32 "
        "{%0,%1,%2,%3}, {%4,%5,%6,%7}, {%8,%9}, {%0,%1,%2,%3};"
        : "+f"(c[0]), "+f"(c[1]), "+f"(c[2]), "+f"(c[3])
        : "r"(a[0]), "r"(a[1]), "r"(a[2]), "r"(a[3]), "r"(b[0]), "r"(b[1]));
}

__global__ void __launch_bounds__(256, 2)
glu_mma_kernel(const float* __restrict__ glu_b, int layer) {
    __shared__ __align__(16) unsigned short sWhi[128 * SPAD];
    __shared__ __align__(16) unsigned short sWlo[128 * SPAD];
    __shared__ __align__(16) unsigned short sGhi[32 * GPAD];
    __shared__ __align__(16) unsigned short sGlo[32 * GPAD];

    const int tid = threadIdx.x;
    const int warp = tid >> 5, lane = tid & 31;
    const int gid = lane >> 2, tig = lane & 3;
    const int warp_m = warp & 3, warp_n = warp >> 2;
    const int j0 = blockIdx.y * 64;
    const int n0 = blockIdx.x * 64;
    const int b = n0 >> 12, l0 = n0 & (Lv - 1);

    const unsigned short* whi_l = g_whi + (size_t)layer * 512 * 256;
    const unsigned short* wlo_l = g_wlo + (size_t)layer * 512 * 256;

    float acc[2][4][4];   // [a,g][ni 0..3][c]
#pragma unroll
    for (int t = 0; t < 2; t++)
#pragma unroll
        for (int n = 0; n < 4; n++)
#pragma unroll
            for (int c = 0; c < 4; c++) acc[t][n][c] = 0.f;

    // ldmatrix addressing
    const int lrow = lane & 15;            // A: row within 16
    const int lcol8 = (lane >> 4) * 8;     // A: k-half
    const int brow = lane & 7;             // B: k-row within 8
    const int bmat = lane >> 3;            // B: matrix index 0..3

    for (int kc = 0; kc < Hv; kc += KC) {
        __syncthreads();
        // W tile: 128 rows x KC halves, uint4 copies (2 per thread per plane)
#pragma unroll
        for (int it = 0; it < 2; it++) {
            int i = tid + it * 256;        // 0..511
            int row = i >> 2;
            int j8 = (i & 3) * 8;
            int grow = (row < 64) ? (j0 + row) : (256 + j0 + row - 64);
            *(uint4*)&sWhi[row * SPAD + j8] = *(const uint4*)&whi_l[grow * Hv + kc + j8];
            *(uint4*)&sWlo[row * SPAD + j8] = *(const uint4*)&wlo_l[grow * Hv + kc + j8];
        }
        // G tile: KC rows (h) x 64 halves (l), uint4 copies (1 per thread per plane)
        {
            int h = tid >> 3;
            int j8 = (tid & 7) * 8;
            size_t gsrc = ((size_t)(b * Hv + kc + h)) * Lv + l0 + j8;
            *(uint4*)&sGhi[h * GPAD + j8] = *(const uint4*)&g_ghi[gsrc];
            *(uint4*)&sGlo[h * GPAD + j8] = *(const uint4*)&g_glo[gsrc];
        }
        __syncthreads();

#pragma unroll
        for (int ks = 0; ks < KC / 16; ks++) {
            const int kb = ks * 16;
            // A fragments: t4=0 -> a rows, t4=1 -> g rows
            unsigned ahi[2][4], alo[2][4];
#pragma unroll
            for (int t4 = 0; t4 < 2; t4++) {
                int rowb = (t4 ? 64 : 0) + 16 * warp_m;
                ldsm4(ahi[t4][0], ahi[t4][1], ahi[t4][2], ahi[t4][3],
                      &sWhi[(rowb + lrow) * SPAD + kb + lcol8]);
                ldsm4(alo[t4][0], alo[t4][1], alo[t4][2], alo[t4][3],
                      &sWlo[(rowb + lrow) * SPAD + kb + lcol8]);
            }
            // B fragments via ldmatrix.trans on [k][l]: 32 cols per warp
            unsigned bhi[4][2], blo[4][2];
#pragma unroll
            for (int half = 0; half < 2; half++) {
                int nb = 32 * warp_n + 16 * half;
                int krow = kb + 8 * (bmat & 1) + brow;
                int ncol = nb + 8 * (bmat >> 1);
                unsigned q0, q1, q2, q3;
                ldsm4t(q0, q1, q2, q3, &sGhi[krow * GPAD + ncol]);
                bhi[2 * half][0] = q0; bhi[2 * half][1] = q1;
                bhi[2 * half + 1][0] = q2; bhi[2 * half + 1][1] = q3;
                ldsm4t(q0, q1, q2, q3, &sGlo[krow * GPAD + ncol]);
                blo[2 * half][0] = q0; blo[2 * half][1] = q1;
                blo[2 * half + 1][0] = q2; blo[2 * half + 1][1] = q3;
            }
#pragma unroll
            for (int t4 = 0; t4 < 2; t4++)
#pragma unroll
                for (int ni = 0; ni < 4; ni++) {
                    mma16816(acc[t4][ni], ahi[t4], bhi[ni]);
                    mma16816(acc[t4][ni], ahi[t4], blo[ni]);
                    mma16816(acc[t4][ni], alo[t4], bhi[ni]);
                }
        }
    }

    // epilogue: bias + GLU gate + store fp32
    const float* bbase = glu_b + (size_t)layer * 512;
    {
        int r0 = j0 + 16 * warp_m + gid;
        float ba0 = bbase[r0],       ba1 = bbase[r0 + 8];
        float bg0 = bbase[r0 + 256], bg1 = bbase[r0 + 264];
#pragma unroll
        for (int ni = 0; ni < 4; ni++) {
            int lcol = l0 + 32 * warp_n + 8 * ni + 2 * tig;
            float a0 = acc[0][ni][0] + ba0, a1 = acc[0][ni][1] + ba0;
            float a2 = acc[0][ni][2] + ba1, a3 = acc[0][ni][3] + ba1;
            float q0 = acc[1][ni][0] + bg0, q1 = acc[1][ni][1] + bg0;
            float q2 = acc[1][ni][2] + bg1, q3 = acc[1][ni][3] + bg1;
            float z0 = a0 * (1.f / (1.f + expf(-q0)));
            float z1 = a1 * (1.f / (1.f + expf(-q1)));
            float z2 = a2 * (1.f / (1.f + expf(-q2)));
            float z3 = a3 * (1.f / (1.f + expf(-q3)));
            *(float2*)&g_z[((size_t)(b * Hv + r0)) * Lv + lcol]     = make_float2(z0, z1);
            *(float2*)&g_z[((size_t)(b * Hv + r0 + 8)) * Lv + lcol] = make_float2(z2, z3);
        }
    }
}

// ---------------------------------------------------------------------------
// Residual + LayerNorm, single-pass smem tile: block per 32 (b,l) columns.
// ---------------------------------------------------------------------------
__global__ void __launch_bounds__(256)
ln_kernel(const float* __restrict__ ln_g,
          const float* __restrict__ ln_b,
          int layer) {
    __shared__ float sv[256][33];
    __shared__ float red[2][8][32];
    __shared__ float smu[32], srs[32];

    const int tid = threadIdx.x;
    const int c = tid & 31, hg = tid >> 5;
    const int col0 = blockIdx.x * 32;
    const int b = col0 >> 12;
    const int l0 = col0 & (Lv - 1);

    float s = 0.f, s2 = 0.f;
#pragma unroll 8
    for (int i = 0; i < 32; i++) {
        int h = hg * 32 + i;
        size_t idx = ((size_t)(b * Hv + h)) * Lv + l0 + c;
        float v = g_z[idx] + g_h[idx];
        sv[h][c] = v;
        s += v;
        s2 = fmaf(v, v, s2);
    }
    red[0][hg][c] = s;
    red[1][hg][c] = s2;
    __syncthreads();
    if (hg == 0) {
        float ts = 0.f, ts2 = 0.f;
#pragma unroll
        for (int g = 0; g < 8; g++) { ts += red[0][g][c]; ts2 += red[1][g][c]; }
        float mu = ts * (1.f / Hv);
        smu[c] = mu;
        srs[c] = rsqrtf(ts2 * (1.f / Hv) - mu * mu + LN_EPS);
    }
    __syncthreads();
    const float mu = smu[c], rs = srs[c];
    const float* lg = ln_g + layer * Hv;
    const float* lb = ln_b + layer * Hv;
#pragma unroll 8
    for (int i = 0; i < 32; i++) {
        int h = hg * 32 + i;
        float v = (sv[h][c] - mu) * rs;
        g_h[((size_t)(b * Hv + h)) * Lv + l0 + c] = fmaf(v, lg[h], lb[h]);
    }
}

// ---------------------------------------------------------------------------
// Decoder
// ---------------------------------------------------------------------------
__global__ void __launch_bounds__(256)
dec_kernel(const float* __restrict__ dec1_w,
           const float* __restrict__ dec1_b,
           const float* __restrict__ dec2_w,
           const float* __restrict__ dec2_b,
           float* __restrict__ out) {
    int b = blockIdx.x;
    int j = threadIdx.x;
    const float* hr = g_h + ((size_t)(b * Hv + j)) * Lv;
    float acc = 0.f;
    for (int l = 0; l < Lv; l += 4) {
        float4 hv = *(const float4*)&hr[l];
        float4 wv = *(const float4*)&dec1_w[l];
        acc = fmaf(hv.x, wv.x, acc);
        acc = fmaf(hv.y, wv.y, acc);
        acc = fmaf(hv.z, wv.z, acc);
        acc = fmaf(hv.w, wv.w, acc);
    }
    acc += dec1_b[0];
    acc *= dec2_w[j];

    __shared__ float red[256];
    red[j] = acc;
    __syncthreads();
#pragma unroll
    for (int off = 128; off > 0; off >>= 1) {
        if (j < off) red[j] += red[j + off];
        __syncthreads();
    }
    if (j == 0) {
        float y = red[0] + dec2_b[0];
        out[b] = 1.f / (1.f + expf(-y));
    }
}

// ---------------------------------------------------------------------------
extern "C" void kernel_launch(void* const* d_in, const int* in_sizes, int n_in,
                              void* d_out, int out_size) {
    const float* x          = (const float*)d_in[0];
    const float* enc_w      = (const float*)d_in[1];
    const float* enc_b      = (const float*)d_in[2];
    const float* log_dt     = (const float*)d_in[3];
    const float* log_A_real = (const float*)d_in[4];
    const float* A_imag     = (const float*)d_in[5];
    const float* C_re       = (const float*)d_in[6];
    const float* C_im       = (const float*)d_in[7];
    const float* Dp         = (const float*)d_in[8];
    const float* glu_w      = (const float*)d_in[9];
    const float* glu_b      = (const float*)d_in[10];
    const float* ln_g       = (const float*)d_in[11];
    const float* ln_b       = (const float*)d_in[12];
    const float* dec1_w     = (const float*)d_in[13];
    const float* dec1_b     = (const float*)d_in[14];
    const float* dec2_w     = (const float*)d_in[15];
    const float* dec2_b     = (const float*)d_in[16];
    float* out = (float*)d_out;

    enc_kernel<<<32768, 256>>>(x, enc_w, enc_b);
    wconv_kernel<<<NLv * 512, 256>>>(glu_w);

    for (int layer = 0; layer < NLv; layer++) {
        scan_gelu_kernel<<<Bv * Hv, 256>>>(
            log_dt, log_A_real, A_imag, C_re, C_im, Dp, layer);
        glu_mma_kernel<<<dim3((Bv * Lv) / 64, Hv / 64), 256>>>(glu_b, layer);
        ln_kernel<<<(Bv * Lv) / 32, 256>>>(ln_g, ln_b, layer);
    }

    dec_kernel<<<Bv, 256>>>(dec1_w, dec1_b, dec2_w, dec2_b, out);
}

// round 17
// speedup vs baseline: 2.3420x; 1.1023x over previous
#include <cuda_runtime.h>
#include <cuda_bf16.h>
#include <math.h>

// Problem constants
#define Bv 32
#define Lv 4096
#define Hv 256
#define NLv 4
#define N2v 32
#define LN_EPS 1e-5f

// Scratch (allocation-free rule: device globals)
__device__ float g_h[(size_t)Bv * Hv * Lv];   // activations (B,H,L) fp32
__device__ float g_z[(size_t)Bv * Hv * Lv];   // GLU output fp32
__device__ unsigned short g_ghi[(size_t)Bv * Hv * Lv];  // gelu bf16 hi plane
__device__ unsigned short g_glo[(size_t)Bv * Hv * Lv];  // gelu bf16 lo plane
__device__ unsigned short g_whi[NLv * 512 * 256];       // W bf16 hi plane
__device__ unsigned short g_wlo[NLv * 512 * 256];       // W bf16 lo plane

// ---------------------------------------------------------------------------
// helpers
// ---------------------------------------------------------------------------
typedef unsigned long long u64p;
__device__ __forceinline__ u64p pk2(float lo, float hi) {
    u64p r; asm("mov.b64 %0, {%1,%2};" : "=l"(r) : "f"(lo), "f"(hi)); return r;
}
__device__ __forceinline__ void upk2(u64p v, float& lo, float& hi) {
    asm("mov.b64 {%0,%1}, %2;" : "=f"(lo), "=f"(hi) : "l"(v));
}
__device__ __forceinline__ u64p fma2(u64p a, u64p b, u64p c) {
    u64p d; asm("fma.rn.f32x2 %0, %1, %2, %3;" : "=l"(d) : "l"(a), "l"(b), "l"(c)); return d;
}
__device__ __forceinline__ u64p mul2(u64p a, u64p b) {
    u64p d; asm("mul.rn.f32x2 %0, %1, %2;" : "=l"(d) : "l"(a), "l"(b)); return d;
}
__device__ __forceinline__ void bf16split2(float x, unsigned short& h, unsigned short& l) {
    __nv_bfloat16 hb = __float2bfloat16(x);
    float hf = __bfloat162float(hb);
    __nv_bfloat16 lb = __float2bfloat16(x - hf);
    h = __bfloat16_as_ushort(hb);
    l = __bfloat16_as_ushort(lb);
}
__device__ __forceinline__ void ldsm4(unsigned& r0, unsigned& r1, unsigned& r2, unsigned& r3,
                                      const void* p) {
    unsigned a = (unsigned)__cvta_generic_to_shared(p);
    asm volatile("ldmatrix.sync.aligned.m8n8.x4.shared.b16 {%0,%1,%2,%3}, [%4];"
                 : "=r"(r0), "=r"(r1), "=r"(r2), "=r"(r3) : "r"(a));
}
__device__ __forceinline__ void ldsm4t(unsigned& r0, unsigned& r1, unsigned& r2, unsigned& r3,
                                       const void* p) {
    unsigned a = (unsigned)__cvta_generic_to_shared(p);
    asm volatile("ldmatrix.sync.aligned.m8n8.x4.trans.shared.b16 {%0,%1,%2,%3}, [%4];"
                 : "=r"(r0), "=r"(r1), "=r"(r2), "=r"(r3) : "r"(a));
}
__device__ __forceinline__ void cpa16(void* dst, const void* src) {
    unsigned d = (unsigned)__cvta_generic_to_shared(dst);
    asm volatile("cp.async.cg.shared.global [%0], [%1], 16;" :: "r"(d), "l"(src));
}
#define CPA_COMMIT() asm volatile("cp.async.commit_group;" ::: "memory")
#define CPA_WAIT(n)  asm volatile("cp.async.wait_group %0;" :: "n"(n) : "memory")

// ---------------------------------------------------------------------------
// Encoder
// ---------------------------------------------------------------------------
__global__ void enc_kernel(const float* __restrict__ x,
                           const float* __restrict__ enc_w,
                           const float* __restrict__ enc_b) {
    size_t t = (size_t)blockIdx.x * blockDim.x + threadIdx.x;
    size_t idx4 = t * 4;
    int l = (int)(idx4 & (Lv - 1));
    int j = (int)((idx4 >> 12) & (Hv - 1));
    int b = (int)(idx4 >> 20);
    float w = enc_w[j];
    float bias = enc_b[j];
    const float4 xv = *(const float4*)&x[(size_t)b * Lv + l];
    float4 o;
    o.x = fmaf(xv.x, w, bias);
    o.y = fmaf(xv.y, w, bias);
    o.z = fmaf(xv.z, w, bias);
    o.w = fmaf(xv.w, w, bias);
    *(float4*)&g_h[idx4] = o;
}

// ---------------------------------------------------------------------------
// W conversion: split all layers' glu_w into bf16 hi/lo planes
// ---------------------------------------------------------------------------
__global__ void wconv_kernel(const float* __restrict__ glu_w) {
    int i = blockIdx.x * 256 + threadIdx.x;
    unsigned short h, l;
    bf16split2(glu_w[i], h, l);
    g_whi[i] = h;
    g_wlo[i] = l;
}

// ---------------------------------------------------------------------------
// Segment-parallel S4D scan + D skip + GELU + bf16 hi/lo plane store.
// ---------------------------------------------------------------------------
#define NSEG 64
#define SGT 64

__global__ void __launch_bounds__(256)
scan_gelu_kernel(const float* __restrict__ log_dt,
                 const float* __restrict__ log_A_real,
                 const float* __restrict__ A_imag,
                 const float* __restrict__ C_re,
                 const float* __restrict__ C_im,
                 const float* __restrict__ Dp,
                 int layer) {
    __shared__ float su[NSEG * 65];
    __shared__ float2 sE[NSEG][33];
    __shared__ float4 sCoef[32];

    const int tid = threadIdx.x;
    const int sub = tid & 3;
    const int seg = tid >> 2;
    const int seq = blockIdx.x;
    const int hh = seq & (Hv - 1);
    const size_t base = (size_t)seq * Lv;

#pragma unroll
    for (int it = 0; it < 4; it++) {
        int i = it * 256 + tid;
        float4 v = *(const float4*)&g_h[base + (size_t)i * 4];
        int sg = i >> 4;
        int l = (i & 15) * 4;
        float* p = &su[sg * 65 + l];
        p[0] = v.x; p[1] = v.y; p[2] = v.z; p[3] = v.w;
    }

    if (tid < 32) {
        int n = tid;
        const int pb = (layer * Hv + hh) * N2v + n;
        float dt = expf(log_dt[layer * Hv + hh]);
        float Ar = -expf(log_A_real[pb]);
        float Ai = A_imag[pb];
        float dAr = Ar * dt, dAi = Ai * dt;
        float e = expf(dAr);
        float lrr = e * cosf(dAi);
        float lii = e * sinf(dAi);
        float cr = C_re[pb], ci = C_im[pb];
        float nr = cr * (lrr - 1.f) - ci * lii;
        float ni = cr * lii + ci * (lrr - 1.f);
        float inv = 1.f / (Ar * Ar + Ai * Ai);
        float ckr =  2.f * (nr * Ar + ni * Ai) * inv;
        float cki = -2.f * (ni * Ar - nr * Ai) * inv;
        sCoef[n] = make_float4(lrr, lii, ckr, cki);
    }
    __syncthreads();

    u64p lr2[4], li2[4], nli2[4], ckr2[4], cki2[4], sr2[4], si2[4];
#pragma unroll
    for (int p = 0; p < 4; p++) {
        float4 c0 = sCoef[sub * 8 + 2 * p];
        float4 c1 = sCoef[sub * 8 + 2 * p + 1];
        lr2[p]  = pk2(c0.x, c1.x);
        li2[p]  = pk2(c0.y, c1.y);
        nli2[p] = pk2(-c0.y, -c1.y);
        ckr2[p] = pk2(c0.z, c1.z);
        cki2[p] = pk2(c0.w, c1.w);
        sr2[p] = 0ull; si2[p] = 0ull;
    }
    const float Dh = Dp[layer * Hv + hh];
    float* sus = &su[seg * 65];

#pragma unroll 4
    for (int l = 0; l < SGT; l++) {
        float u = sus[l];
        u64p u2 = pk2(u, u);
#pragma unroll
        for (int p = 0; p < 4; p++) {
            u64p nr = fma2(lr2[p], sr2[p], u2);
            nr = fma2(nli2[p], si2[p], nr);
            u64p ni = fma2(li2[p], sr2[p], mul2(lr2[p], si2[p]));
            sr2[p] = nr; si2[p] = ni;
        }
    }
#pragma unroll
    for (int p = 0; p < 4; p++) {
        float r0, r1, i0, i1;
        upk2(sr2[p], r0, r1);
        upk2(si2[p], i0, i1);
        sE[seg][sub * 8 + 2 * p]     = make_float2(r0, i0);
        sE[seg][sub * 8 + 2 * p + 1] = make_float2(r1, i1);
    }
    __syncthreads();

    if (tid < 32) {
        float4 c = sCoef[tid];
        float tr = c.x, ti = c.y;
#pragma unroll
        for (int q = 0; q < 6; q++) {
            float nr = tr * tr - ti * ti;
            float ni = 2.f * tr * ti;
            tr = nr; ti = ni;
        }
        float sr = 0.f, si = 0.f;
        for (int cseg = 0; cseg < NSEG; cseg++) {
            float2 e = sE[cseg][tid];
            sE[cseg][tid] = make_float2(sr, si);
            float nr = tr * sr - ti * si + e.x;
            float ni = tr * si + ti * sr + e.y;
            sr = nr; si = ni;
        }
    }
    __syncthreads();

#pragma unroll
    for (int p = 0; p < 4; p++) {
        float2 a = sE[seg][sub * 8 + 2 * p];
        float2 b2 = sE[seg][sub * 8 + 2 * p + 1];
        sr2[p] = pk2(a.x, b2.x);
        si2[p] = pk2(a.y, b2.y);
    }
#pragma unroll 4
    for (int l = 0; l < SGT; l++) {
        float u = sus[l];
        u64p u2 = pk2(u, u);
        u64p acc2 = 0ull;
#pragma unroll
        for (int p = 0; p < 4; p++) {
            u64p nr = fma2(lr2[p], sr2[p], u2);
            nr = fma2(nli2[p], si2[p], nr);
            u64p ni = fma2(li2[p], sr2[p], mul2(lr2[p], si2[p]));
            sr2[p] = nr; si2[p] = ni;
            acc2 = fma2(ckr2[p], nr, acc2);
            acc2 = fma2(cki2[p], ni, acc2);
        }
        float a0, a1; upk2(acc2, a0, a1);
        float acc = a0 + a1;
        acc += __shfl_xor_sync(0xffffffffu, acc, 1);
        acc += __shfl_xor_sync(0xffffffffu, acc, 2);
        if (sub == 0) sus[l] = fmaf(Dh, u, acc);
    }
    __syncthreads();

#pragma unroll
    for (int it = 0; it < 8; it++) {
        int i2 = it * 256 + tid;
        int li = i2 * 2;
        int sg = li >> 6;
        int l = li & 63;
        float y0 = su[sg * 65 + l];
        float y1 = su[sg * 65 + l + 1];
        float ge0 = 0.5f * y0 * (1.f + erff(y0 * 0.70710678118654752f));
        float ge1 = 0.5f * y1 * (1.f + erff(y1 * 0.70710678118654752f));
        unsigned short h0, l0b, h1, l1b;
        bf16split2(ge0, h0, l0b);
        bf16split2(ge1, h1, l1b);
        *(unsigned*)&g_ghi[base + li] = (unsigned)h0 | ((unsigned)h1 << 16);
        *(unsigned*)&g_glo[base + li] = (unsigned)l0b | ((unsigned)l1b << 16);
    }
}

// ---------------------------------------------------------------------------
// GLU GEMM, mma.m16n8k16 bf16 hi/lo split, cp.async double-buffered pipeline.
// W in smem [j][k] (ldmatrix), G in smem [k][l] (ldmatrix.trans).
// Tile: (64 a-rows + 64 g-rows) x 64 cols; 8 warps = 4 warp_m x 2 warp_n.
// ---------------------------------------------------------------------------
#define KC 32
#define SPAD 40   // W row stride in u16 (80B)
#define GPAD 72   // G row stride in u16 (144B)
#define WPLANE (128 * SPAD)          // u16 per W plane buffer
#define GPLANE (32 * GPAD)           // u16 per G plane buffer
// layout (u16 units): Whi[2], Wlo[2], Ghi[2], Glo[2]
#define OFF_WHI(bf) ((bf) * WPLANE)
#define OFF_WLO(bf) (2 * WPLANE + (bf) * WPLANE)
#define OFF_GHI(bf) (4 * WPLANE + (bf) * GPLANE)
#define OFF_GLO(bf) (4 * WPLANE + 2 * GPLANE + (bf) * GPLANE)
#define GLU_DSMEM ((4 * WPLANE + 4 * GPLANE) * 2)

__device__ __forceinline__ void mma16816(float* c, const unsigned* a, const unsigned* b) {
    asm volatile(
        "mma.sync.aligned.m16n8k16.row.col.f32.bf16.bf16.f32 "
        "{%0,%1,%2,%3}, {%4,%5,%6,%7}, {%8,%9}, {%0,%1,%2,%3};"
        : "+f"(c[0]), "+f"(c[1]), "+f"(c[2]), "+f"(c[3])
        : "r"(a[0]), "r"(a[1]), "r"(a[2]), "r"(a[3]), "r"(b[0]), "r"(b[1]));
}

__global__ void __launch_bounds__(256, 2)
glu_mma_kernel(const float* __restrict__ glu_b, int layer) {
    extern __shared__ __align__(16) unsigned short smem[];

    const int tid = threadIdx.x;
    const int warp = tid >> 5, lane = tid & 31;
    const int gid = lane >> 2, tig = lane & 3;
    const int warp_m = warp & 3, warp_n = warp >> 2;
    const int j0 = blockIdx.y * 64;
    const int n0 = blockIdx.x * 64;
    const int b = n0 >> 12, l0 = n0 & (Lv - 1);

    const unsigned short* whi_l = g_whi + (size_t)layer * 512 * 256;
    const unsigned short* wlo_l = g_wlo + (size_t)layer * 512 * 256;

    float acc[2][4][4];
#pragma unroll
    for (int t = 0; t < 2; t++)
#pragma unroll
        for (int n = 0; n < 4; n++)
#pragma unroll
            for (int c = 0; c < 4; c++) acc[t][n][c] = 0.f;

    // staging indices (fixed per thread)
    const int wrow0 = tid >> 2;                 // 0..63
    const int wq = (tid & 3) * 8;               // 16B chunk within KC=32
    const int grow0 = (wrow0 < 64) ? (j0 + wrow0) : 0;       // unused guard
    const int gh = tid >> 3;                    // 0..31 (k row)
    const int gq = (tid & 7) * 8;               // l chunk
    const size_t gsrc_base = ((size_t)(b * Hv + gh)) * Lv + l0 + gq;

    // stage chunk kc into buffer bf
    auto stage = [&](int bf, int kc) {
#pragma unroll
        for (int it = 0; it < 2; it++) {
            int row = wrow0 + it * 64;           // 0..127
            int grow = (row < 64) ? (j0 + row) : (256 + j0 + row - 64);
            size_t src = (size_t)grow * Hv + kc + wq;
            cpa16(&smem[OFF_WHI(bf) + row * SPAD + wq], &whi_l[src]);
            cpa16(&smem[OFF_WLO(bf) + row * SPAD + wq], &wlo_l[src]);
        }
        size_t gsrc = gsrc_base + (size_t)kc * Lv;
        cpa16(&smem[OFF_GHI(bf) + gh * GPAD + gq], &g_ghi[gsrc]);
        cpa16(&smem[OFF_GLO(bf) + gh * GPAD + gq], &g_glo[gsrc]);
    };

    const int lrow = lane & 15;
    const int lcol8 = (lane >> 4) * 8;
    const int brow = lane & 7;
    const int bmat = lane >> 3;

    stage(0, 0);
    CPA_COMMIT();

    for (int kci = 0; kci < Hv / KC; kci++) {
        const int bf = kci & 1;
        if (kci + 1 < Hv / KC) {
            stage(bf ^ 1, (kci + 1) * KC);
            CPA_COMMIT();
            CPA_WAIT(1);
        } else {
            CPA_WAIT(0);
        }
        __syncthreads();

        const unsigned short* sWhi = &smem[OFF_WHI(bf)];
        const unsigned short* sWlo = &smem[OFF_WLO(bf)];
        const unsigned short* sGhi = &smem[OFF_GHI(bf)];
        const unsigned short* sGlo = &smem[OFF_GLO(bf)];

#pragma unroll
        for (int ks = 0; ks < KC / 16; ks++) {
            const int kb = ks * 16;
            unsigned ahi[2][4], alo[2][4];
#pragma unroll
            for (int t4 = 0; t4 < 2; t4++) {
                int rowb = (t4 ? 64 : 0) + 16 * warp_m;
                ldsm4(ahi[t4][0], ahi[t4][1], ahi[t4][2], ahi[t4][3],
                      &sWhi[(rowb + lrow) * SPAD + kb + lcol8]);
                ldsm4(alo[t4][0], alo[t4][1], alo[t4][2], alo[t4][3],
                      &sWlo[(rowb + lrow) * SPAD + kb + lcol8]);
            }
            unsigned bhi[4][2], blo[4][2];
#pragma unroll
            for (int half = 0; half < 2; half++) {
                int nb = 32 * warp_n + 16 * half;
                int krow = kb + 8 * (bmat & 1) + brow;
                int ncol = nb + 8 * (bmat >> 1);
                unsigned q0, q1, q2, q3;
                ldsm4t(q0, q1, q2, q3, &sGhi[krow * GPAD + ncol]);
                bhi[2 * half][0] = q0; bhi[2 * half][1] = q1;
                bhi[2 * half + 1][0] = q2; bhi[2 * half + 1][1] = q3;
                ldsm4t(q0, q1, q2, q3, &sGlo[krow * GPAD + ncol]);
                blo[2 * half][0] = q0; blo[2 * half][1] = q1;
                blo[2 * half + 1][0] = q2; blo[2 * half + 1][1] = q3;
            }
#pragma unroll
            for (int t4 = 0; t4 < 2; t4++)
#pragma unroll
                for (int ni = 0; ni < 4; ni++) {
                    mma16816(acc[t4][ni], ahi[t4], bhi[ni]);
                    mma16816(acc[t4][ni], ahi[t4], blo[ni]);
                    mma16816(acc[t4][ni], alo[t4], bhi[ni]);
                }
        }
        __syncthreads();
    }

    // epilogue: bias + GLU gate + store fp32
    const float* bbase = glu_b + (size_t)layer * 512;
    {
        int r0 = j0 + 16 * warp_m + gid;
        float ba0 = bbase[r0],       ba1 = bbase[r0 + 8];
        float bg0 = bbase[r0 + 256], bg1 = bbase[r0 + 264];
#pragma unroll
        for (int ni = 0; ni < 4; ni++) {
            int lcol = l0 + 32 * warp_n + 8 * ni + 2 * tig;
            float a0 = acc[0][ni][0] + ba0, a1 = acc[0][ni][1] + ba0;
            float a2 = acc[0][ni][2] + ba1, a3 = acc[0][ni][3] + ba1;
            float q0 = acc[1][ni][0] + bg0, q1 = acc[1][ni][1] + bg0;
            float q2 = acc[1][ni][2] + bg1, q3 = acc[1][ni][3] + bg1;
            float z0 = a0 * (1.f / (1.f + expf(-q0)));
            float z1 = a1 * (1.f / (1.f + expf(-q1)));
            float z2 = a2 * (1.f / (1.f + expf(-q2)));
            float z3 = a3 * (1.f / (1.f + expf(-q3)));
            *(float2*)&g_z[((size_t)(b * Hv + r0)) * Lv + lcol]     = make_float2(z0, z1);
            *(float2*)&g_z[((size_t)(b * Hv + r0 + 8)) * Lv + lcol] = make_float2(z2, z3);
        }
    }
}

// ---------------------------------------------------------------------------
// Residual + LayerNorm, single-pass smem tile: block per 32 (b,l) columns.
// ---------------------------------------------------------------------------
__global__ void __launch_bounds__(256)
ln_kernel(const float* __restrict__ ln_g,
          const float* __restrict__ ln_b,
          int layer) {
    __shared__ float sv[256][33];
    __shared__ float red[2][8][32];
    __shared__ float smu[32], srs[32];

    const int tid = threadIdx.x;
    const int c = tid & 31, hg = tid >> 5;
    const int col0 = blockIdx.x * 32;
    const int b = col0 >> 12;
    const int l0 = col0 & (Lv - 1);

    float s = 0.f, s2 = 0.f;
#pragma unroll 8
    for (int i = 0; i < 32; i++) {
        int h = hg * 32 + i;
        size_t idx = ((size_t)(b * Hv + h)) * Lv + l0 + c;
        float v = g_z[idx] + g_h[idx];
        sv[h][c] = v;
        s += v;
        s2 = fmaf(v, v, s2);
    }
    red[0][hg][c] = s;
    red[1][hg][c] = s2;
    __syncthreads();
    if (hg == 0) {
        float ts = 0.f, ts2 = 0.f;
#pragma unroll
        for (int g = 0; g < 8; g++) { ts += red[0][g][c]; ts2 += red[1][g][c]; }
        float mu = ts * (1.f / Hv);
        smu[c] = mu;
        srs[c] = rsqrtf(ts2 * (1.f / Hv) - mu * mu + LN_EPS);
    }
    __syncthreads();
    const float mu = smu[c], rs = srs[c];
    const float* lg = ln_g + layer * Hv;
    const float* lb = ln_b + layer * Hv;
#pragma unroll 8
    for (int i = 0; i < 32; i++) {
        int h = hg * 32 + i;
        float v = (sv[h][c] - mu) * rs;
        g_h[((size_t)(b * Hv + h)) * Lv + l0 + c] = fmaf(v, lg[h], lb[h]);
    }
}

// ---------------------------------------------------------------------------
// Decoder
// ---------------------------------------------------------------------------
__global__ void __launch_bounds__(256)
dec_kernel(const float* __restrict__ dec1_w,
           const float* __restrict__ dec1_b,
           const float* __restrict__ dec2_w,
           const float* __restrict__ dec2_b,
           float* __restrict__ out) {
    int b = blockIdx.x;
    int j = threadIdx.x;
    const float* hr = g_h + ((size_t)(b * Hv + j)) * Lv;
    float acc = 0.f;
    for (int l = 0; l < Lv; l += 4) {
        float4 hv = *(const float4*)&hr[l];
        float4 wv = *(const float4*)&dec1_w[l];
        acc = fmaf(hv.x, wv.x, acc);
        acc = fmaf(hv.y, wv.y, acc);
        acc = fmaf(hv.z, wv.z, acc);
        acc = fmaf(hv.w, wv.w, acc);
    }
    acc += dec1_b[0];
    acc *= dec2_w[j];

    __shared__ float red[256];
    red[j] = acc;
    __syncthreads();
#pragma unroll
    for (int off = 128; off > 0; off >>= 1) {
        if (j < off) red[j] += red[j + off];
        __syncthreads();
    }
    if (j == 0) {
        float y = red[0] + dec2_b[0];
        out[b] = 1.f / (1.f + expf(-y));
    }
}

// ---------------------------------------------------------------------------
extern "C" void kernel_launch(void* const* d_in, const int* in_sizes, int n_in,
                              void* d_out, int out_size) {
    const float* x          = (const float*)d_in[0];
    const float* enc_w      = (const float*)d_in[1];
    const float* enc_b      = (const float*)d_in[2];
    const float* log_dt     = (const float*)d_in[3];
    const float* log_A_real = (const float*)d_in[4];
    const float* A_imag     = (const float*)d_in[5];
    const float* C_re       = (const float*)d_in[6];
    const float* C_im       = (const float*)d_in[7];
    const float* Dp         = (const float*)d_in[8];
    const float* glu_w      = (const float*)d_in[9];
    const float* glu_b      = (const float*)d_in[10];
    const float* ln_g       = (const float*)d_in[11];
    const float* ln_b       = (const float*)d_in[12];
    const float* dec1_w     = (const float*)d_in[13];
    const float* dec1_b     = (const float*)d_in[14];
    const float* dec2_w     = (const float*)d_in[15];
    const float* dec2_b     = (const float*)d_in[16];
    float* out = (float*)d_out;

    static int smem_set = 0;
    if (!smem_set) {
        cudaFuncSetAttribute(glu_mma_kernel,
                             cudaFuncAttributeMaxDynamicSharedMemorySize, GLU_DSMEM);
        smem_set = 1;
    }

    enc_kernel<<<32768, 256>>>(x, enc_w, enc_b);
    wconv_kernel<<<NLv * 512, 256>>>(glu_w);

    for (int layer = 0; layer < NLv; layer++) {
        scan_gelu_kernel<<<Bv * Hv, 256>>>(
            log_dt, log_A_real, A_imag, C_re, C_im, Dp, layer);
        glu_mma_kernel<<<dim3((Bv * Lv) / 64, Hv / 64), 256, GLU_DSMEM>>>(glu_b, layer);
        ln_kernel<<<(Bv * Lv) / 32, 256>>>(ln_g, ln_b, layer);
    }

    dec_kernel<<<Bv, 256>>>(dec1_w, dec1_b, dec2_w, dec2_b, out);
}